// round 7
// baseline (speedup 1.0000x reference)
#include <cuda_runtime.h>
#include <cuda_bf16.h>
#include <cstdint>

#define NN   131072
#define EE   1048576
#define HH   128
#define BBG  512
#define PPG  32
#define NH   (NN*HH)

// ---------------- static device scratch ----------------
__device__ float g_emb[NH];
__device__ float g_h[NH];
__device__ float g_h2[NH];
__device__ float g_xinit[NH];
__device__ float g_m[4ULL * NH];   // y[t][N][128]
__device__ float g_pool[BBG * HH];
__device__ float g_tp[BBG * HH];
__device__ float g_wbt[HH * HH];
// dst-keyed CSR
__device__ int  g_cnt[NN];
__device__ int  g_off[NN + 1];
__device__ int  g_cur[NN];
__device__ int  g_bsum[128];
__device__ int2 g_rec[EE];         // {src | etype<<20, norm bits}

// ---------------- helpers ----------------
__device__ __forceinline__ uint32_t smem_u32(const void* p) {
    uint32_t a;
    asm("{ .reg .u64 t; cvta.to.shared.u64 t, %1; cvt.u32.u64 %0, t; }" : "=r"(a) : "l"(p));
    return a;
}
__device__ __forceinline__ void ldsm_x4(uint32_t r[4], uint32_t addr) {
    asm volatile("ldmatrix.sync.aligned.m8n8.x4.shared.b16 {%0,%1,%2,%3}, [%4];"
                 : "=r"(r[0]), "=r"(r[1]), "=r"(r[2]), "=r"(r[3]) : "r"(addr));
}
__device__ __forceinline__ void ldsm_x4_t(uint32_t r[4], uint32_t addr) {
    asm volatile("ldmatrix.sync.aligned.m8n8.x4.trans.shared.b16 {%0,%1,%2,%3}, [%4];"
                 : "=r"(r[0]), "=r"(r[1]), "=r"(r[2]), "=r"(r[3]) : "r"(addr));
}
__device__ __forceinline__ void mma_bf16(float* c, const uint32_t a[4], const uint32_t* b) {
    asm volatile(
        "mma.sync.aligned.m16n8k16.row.col.f32.bf16.bf16.f32 "
        "{%0,%1,%2,%3}, {%4,%5,%6,%7}, {%8,%9}, {%0,%1,%2,%3};"
        : "+f"(c[0]), "+f"(c[1]), "+f"(c[2]), "+f"(c[3])
        : "r"(a[0]), "r"(a[1]), "r"(a[2]), "r"(a[3]), "r"(b[0]), "r"(b[1]));
}
__device__ __forceinline__ void split2(float a, float b, uint32_t& hi, uint32_t& lo) {
    __nv_bfloat16 ha = __float2bfloat16_rn(a);
    __nv_bfloat16 hb = __float2bfloat16_rn(b);
    __nv_bfloat16 la = __float2bfloat16_rn(a - __bfloat162float(ha));
    __nv_bfloat16 lb = __float2bfloat16_rn(b - __bfloat162float(hb));
    hi = (uint32_t)__bfloat16_as_ushort(ha) | ((uint32_t)__bfloat16_as_ushort(hb) << 16);
    lo = (uint32_t)__bfloat16_as_ushort(la) | ((uint32_t)__bfloat16_as_ushort(lb) << 16);
}

// ---------------- CSR build (dst-keyed) ----------------
__global__ void k_count(const int* __restrict__ dst) {
    int e = blockIdx.x * blockDim.x + threadIdx.x;
    if (e >= EE) return;
    atomicAdd(&g_cnt[dst[e]], 1);
}

__global__ void k_scan1() {
    __shared__ int s[256];
    int t = threadIdx.x;
    int4 v = *(const int4*)(g_cnt + blockIdx.x * 1024 + t * 4);
    s[t] = v.x + v.y + v.z + v.w;
    __syncthreads();
    for (int o = 128; o > 0; o >>= 1) {
        if (t < o) s[t] += s[t + o];
        __syncthreads();
    }
    if (t == 0) g_bsum[blockIdx.x] = s[0];
}

__global__ void k_scan2() {
    __shared__ int s[128];
    int t = threadIdx.x;
    int mine = g_bsum[t];
    s[t] = mine;
    __syncthreads();
    for (int o = 1; o < 128; o <<= 1) {
        int add = (t >= o) ? s[t - o] : 0;
        __syncthreads();
        s[t] += add;
        __syncthreads();
    }
    g_bsum[t] = s[t] - mine;
}

__global__ void k_scan3() {
    __shared__ int s[256];
    int t = threadIdx.x;
    int base = blockIdx.x * 1024 + t * 4;
    int4 v = *(const int4*)(g_cnt + base);
    int tsum = v.x + v.y + v.z + v.w;
    s[t] = tsum;
    __syncthreads();
    for (int o = 1; o < 256; o <<= 1) {
        int add = (t >= o) ? s[t - o] : 0;
        __syncthreads();
        s[t] += add;
        __syncthreads();
    }
    int o0 = s[t] - tsum + g_bsum[blockIdx.x];
    int o1 = o0 + v.x, o2 = o1 + v.y, o3 = o2 + v.z;
    *(int4*)(g_off + base) = make_int4(o0, o1, o2, o3);
    *(int4*)(g_cur + base) = make_int4(o0, o1, o2, o3);
    if (base + 4 == NN) g_off[NN] = o3 + v.w;
}

__global__ void k_fill(const int* __restrict__ src, const int* __restrict__ dst,
                       const int* __restrict__ et,  const float* __restrict__ norm) {
    int e = blockIdx.x * blockDim.x + threadIdx.x;
    if (e >= EE) return;
    int p = atomicAdd(&g_cur[dst[e]], 1);
    g_rec[p] = make_int2(src[e] | (et[e] << 20), __float_as_int(norm[e]));
}

// ---------------- init_forward + xinit (warp per node, CSR) ----------------
__global__ void k_init(const float4* __restrict__ tab, const int* __restrict__ gid,
                       const int* __restrict__ spo, const int* __restrict__ acc_,
                       const int* __restrict__ pre, const float* __restrict__ Wt,
                       const float* __restrict__ bt)
{
    int node = (blockIdx.x * blockDim.x + threadIdx.x) >> 5;
    int lane = threadIdx.x & 31;
    if (node >= NN) return;
    int s0 = spo[node * 3 + 0];
    int s1 = spo[node * 3 + 1];
    int s2 = spo[node * 3 + 2];
    int beg = g_off[node], end = g_off[node + 1];

    float4 a = make_float4(0.f, 0.f, 0.f, 0.f);
    bool has_ne = false;
    for (int base = beg; base < end; base += 32) {
        int n = min(32, end - base);
        int2 r = (base + lane < end) ? g_rec[base + lane] : make_int2(-1, 0);
        for (int i = 0; i < n; i++) {
            int rx = __shfl_sync(0xffffffffu, r.x, i);
            int rn = __shfl_sync(0xffffffffu, r.y, i);
            if ((rx >> 20) != 0) continue;
            has_ne = true;
            int s = rx & 0xFFFFF;
            float nw = __int_as_float(rn);
            float4 hv = tab[(size_t)gid[s] * 32 + lane];
            a.x += hv.x * nw; a.y += hv.y * nw;
            a.z += hv.z * nw; a.w += hv.w * nw;
        }
    }
    float4 e4;
    if ((s0 + s2) > 0 && has_ne) e4 = a;
    else                         e4 = tab[(size_t)gid[node] * 32 + lane];
    ((float4*)g_emb)[(size_t)node * 32 + lane] = e4;

    float coef[5];
    coef[0] = (float)s0; coef[1] = (float)s1; coef[2] = (float)s2;
    coef[3] = (float)acc_[node]; coef[4] = (float)pre[node];
    float4 r = ((const float4*)bt)[lane];
#pragma unroll
    for (int j = 0; j < 5; j++) {
        float4 ww = ((const float4*)(Wt + (size_t)(128 + j) * HH))[lane];
        r.x += coef[j] * ww.x; r.y += coef[j] * ww.y;
        r.z += coef[j] * ww.z; r.w += coef[j] * ww.w;
    }
    ((float4*)g_xinit)[(size_t)node * 32 + lane] = r;
}

// ---------------- dense HMMA GEMM core (occ 2, 64-wide K chunks) ----------------
#define SM_AHI 0
#define SM_ALO 18432
#define SM_BHI 36864
#define SM_BLO 54272
#define SM_TOT 71680

// shared inner machinery for one K-chunk MMA; c is [4][4][4]
__device__ __forceinline__ void gemm_chunk_mma(uint32_t s0, int warp_m, int warp_n,
                                               int lane, float c[4][4][4]) {
#pragma unroll
    for (int ks = 0; ks < 4; ks++) {
        uint32_t ah[4][4], al[4][4];
#pragma unroll
        for (int mt = 0; mt < 4; mt++) {
            uint32_t row  = warp_m * 64 + mt * 16 + (lane & 15);
            uint32_t addr = s0 + SM_AHI + row * 144 + ks * 32 + ((lane >> 4) << 4);
            ldsm_x4(ah[mt], addr);
            ldsm_x4(al[mt], addr + (SM_ALO - SM_AHI));
        }
#pragma unroll
        for (int np = 0; np < 2; np++) {
            uint32_t kk   = ks * 16 + (lane & 15);
            uint32_t col  = warp_n * 32 + np * 16 + ((lane >> 4) & 1) * 8;
            uint32_t addr = s0 + SM_BHI + kk * 272 + col * 2;
            uint32_t bh[4], bl[4];
            ldsm_x4_t(bh, addr);
            ldsm_x4_t(bl, addr + (SM_BLO - SM_BHI));
#pragma unroll
            for (int mt = 0; mt < 4; mt++) {
                mma_bf16(c[mt][np * 2],     ah[mt], bh);
                mma_bf16(c[mt][np * 2],     al[mt], bh);
                mma_bf16(c[mt][np * 2],     ah[mt], bl);
                mma_bf16(c[mt][np * 2 + 1], ah[mt], bh + 2);
                mma_bf16(c[mt][np * 2 + 1], al[mt], bh + 2);
                mma_bf16(c[mt][np * 2 + 1], ah[mt], bl + 2);
            }
        }
    }
}

__device__ __forceinline__ void gemm_load_chunk(char* smem, int tid, int row0,
                                                const float* __restrict__ A,
                                                const float* __restrict__ B, int ch) {
    if (tid < 128) {
        const float* ga = A + (size_t)row0 * HH + ch * 64;
#pragma unroll
        for (int p = 0; p < 16; p++) {
            int e = p * 128 + tid;
            int r = e >> 4, c4 = e & 15;
            float4 v = *(const float4*)(ga + (size_t)r * HH + c4 * 4);
            uint32_t h0, l0, h1, l1;
            split2(v.x, v.y, h0, l0);
            split2(v.z, v.w, h1, l1);
            uint32_t off = (uint32_t)r * 144 + c4 * 8;
            *(uint2*)(smem + SM_AHI + off) = make_uint2(h0, h1);
            *(uint2*)(smem + SM_ALO + off) = make_uint2(l0, l1);
        }
    } else {
        int t = tid - 128;
        const float* gb = B + (size_t)(ch * 64) * HH;
#pragma unroll
        for (int p = 0; p < 16; p++) {
            int e = p * 128 + t;
            int k = e >> 5, c4 = e & 31;
            float4 v = *(const float4*)(gb + (size_t)k * HH + c4 * 4);
            uint32_t h0, l0, h1, l1;
            split2(v.x, v.y, h0, l0);
            split2(v.z, v.w, h1, l1);
            uint32_t off = (uint32_t)k * 272 + c4 * 8;
            *(uint2*)(smem + SM_BHI + off) = make_uint2(h0, h1);
            *(uint2*)(smem + SM_BLO + off) = make_uint2(l0, l1);
        }
    }
}

// input projection: C = A @ B (K=128) + Cadd
__global__ void __launch_bounds__(256, 2) k_gemm_tc(
    const float* __restrict__ A, const float* __restrict__ B,
    const float* __restrict__ Cadd, float* __restrict__ C)
{
    extern __shared__ char smem[];
    uint32_t s0 = smem_u32(smem);
    int tid = threadIdx.x, wid = tid >> 5, lane = tid & 31;
    int row0 = blockIdx.x * 128;
    int warp_m = wid & 1, warp_n = wid >> 1;

    float c[4][4][4];
#pragma unroll
    for (int i = 0; i < 4; i++)
#pragma unroll
        for (int j = 0; j < 4; j++)
#pragma unroll
            for (int q = 0; q < 4; q++) c[i][j][q] = 0.0f;

    for (int ch = 0; ch < 2; ch++) {
        gemm_load_chunk(smem, tid, row0, A, B, ch);
        __syncthreads();
        gemm_chunk_mma(s0, warp_m, warp_n, lane, c);
        __syncthreads();
    }

#pragma unroll
    for (int mt = 0; mt < 4; mt++) {
#pragma unroll
        for (int nt = 0; nt < 4; nt++) {
            int col = warp_n * 32 + nt * 8 + (lane & 3) * 2;
#pragma unroll
            for (int half = 0; half < 2; half++) {
                long row  = row0 + warp_m * 64 + mt * 16 + (lane >> 2) + half * 8;
                long base = row * HH + col;
                float2 v;
                v.x = c[mt][nt][half * 2 + 0];
                v.y = c[mt][nt][half * 2 + 1];
                float2 t = *(const float2*)(Cadd + base);
                v.x += t.x; v.y += t.y;
                *(float2*)(C + base) = v;
            }
        }
    }
}

// layer GEMM: y_t = h @ W_r[l,t]; grid = (N/128, 4), occ 2
__global__ void __launch_bounds__(256, 2) k_gemm_y(
    const float* __restrict__ A, const float* __restrict__ Wl, float* __restrict__ y)
{
    extern __shared__ char smem[];
    uint32_t s0 = smem_u32(smem);
    int tid = threadIdx.x, wid = tid >> 5, lane = tid & 31;
    int row0 = blockIdx.x * 128;
    int t    = blockIdx.y;
    const float* B  = Wl + (size_t)t * HH * HH;
    float*       Ct = y + (size_t)t * NH;
    int warp_m = wid & 1, warp_n = wid >> 1;

    float c[4][4][4];
#pragma unroll
    for (int i = 0; i < 4; i++)
#pragma unroll
        for (int j = 0; j < 4; j++)
#pragma unroll
            for (int q = 0; q < 4; q++) c[i][j][q] = 0.0f;

    for (int ch = 0; ch < 2; ch++) {
        gemm_load_chunk(smem, tid, row0, A, B, ch);
        __syncthreads();
        gemm_chunk_mma(s0, warp_m, warp_n, lane, c);
        __syncthreads();
    }

#pragma unroll
    for (int mt = 0; mt < 4; mt++) {
#pragma unroll
        for (int nt = 0; nt < 4; nt++) {
            int col = warp_n * 32 + nt * 8 + (lane & 3) * 2;
#pragma unroll
            for (int half = 0; half < 2; half++) {
                long row  = row0 + warp_m * 64 + mt * 16 + (lane >> 2) + half * 8;
                long base = row * HH + col;
                *(float2*)(Ct + base) =
                    make_float2(c[mt][nt][half * 2 + 0], c[mt][nt][half * 2 + 1]);
            }
        }
    }
}

// ---------------- CSR gather + bias + relu + residual (warp per dst node) ------
__global__ void k_gather_agg(const float* __restrict__ y, const float* __restrict__ bias,
                             const float* __restrict__ resid, float* __restrict__ out)
{
    int node = (blockIdx.x * blockDim.x + threadIdx.x) >> 5;
    int lane = threadIdx.x & 31;
    if (node >= NN) return;
    int beg = g_off[node], end = g_off[node + 1];

    float4 a = make_float4(0.f, 0.f, 0.f, 0.f);
    for (int base = beg; base < end; base += 32) {
        int n = min(32, end - base);
        int2 r = (base + lane < end) ? g_rec[base + lane] : make_int2(0, 0);
        int i = 0;
        // 4-wide batches: 4 independent loads in flight before FMAs
        for (; i + 4 <= n; i += 4) {
            float4 v[4];
            float  nw[4];
#pragma unroll
            for (int q = 0; q < 4; q++) {
                int rx = __shfl_sync(0xffffffffu, r.x, i + q);
                int rn = __shfl_sync(0xffffffffu, r.y, i + q);
                nw[q] = __int_as_float(rn);
                v[q] = *(const float4*)(y + (size_t)(rx >> 20) * NH
                                          + (size_t)(rx & 0xFFFFF) * HH + lane * 4);
            }
#pragma unroll
            for (int q = 0; q < 4; q++) {
                a.x += v[q].x * nw[q]; a.y += v[q].y * nw[q];
                a.z += v[q].z * nw[q]; a.w += v[q].w * nw[q];
            }
        }
        for (; i < n; i++) {
            int rx = __shfl_sync(0xffffffffu, r.x, i);
            int rn = __shfl_sync(0xffffffffu, r.y, i);
            float nw = __int_as_float(rn);
            float4 v = *(const float4*)(y + (size_t)(rx >> 20) * NH
                                          + (size_t)(rx & 0xFFFFF) * HH + lane * 4);
            a.x += v.x * nw; a.y += v.y * nw;
            a.z += v.z * nw; a.w += v.w * nw;
        }
    }
    float4 b = ((const float4*)bias)[lane];
    float4 v;
    v.x = fmaxf(a.x + b.x, 0.f);
    v.y = fmaxf(a.y + b.y, 0.f);
    v.z = fmaxf(a.z + b.z, 0.f);
    v.w = fmaxf(a.w + b.w, 0.f);
    if (resid) {
        float4 rr = ((const float4*)resid)[(size_t)node * 32 + lane];
        v.x += rr.x; v.y += rr.y; v.z += rr.z; v.w += rr.w;
    }
    ((float4*)out)[(size_t)node * 32 + lane] = v;
}

// ---------------- head kernels ----------------
__global__ void k_transpose(const float* __restrict__ Wb) {
    int idx = blockIdx.x * blockDim.x + threadIdx.x;
    if (idx >= HH * HH) return;
    int r = idx >> 7, c = idx & 127;
    g_wbt[c * HH + r] = Wb[idx];
}

__global__ void k_pool(const float* __restrict__ h, const int* __restrict__ pred) {
    int b = blockIdx.x, j = threadIdx.x;
    float acc = 0.0f;
#pragma unroll 4
    for (int p = 0; p < PPG; p++) {
        int node = pred[b * PPG + p];
        acc += h[(size_t)node * HH + j];
    }
    g_pool[b * HH + j] = acc * (1.0f / PPG);
}

__global__ void k_tp() {
    int b = blockIdx.x, hrow = threadIdx.x;
    __shared__ float ps[HH];
    ps[hrow] = g_pool[b * HH + hrow];
    __syncthreads();
    float acc = 0.0f;
#pragma unroll 8
    for (int k = 0; k < HH; k++)
        acc += g_wbt[(size_t)k * HH + hrow] * ps[k];
    g_tp[b * HH + hrow] = acc;
}

__global__ void k_score(const float* __restrict__ h, const int* __restrict__ pred,
                        const float* __restrict__ bbp, float* __restrict__ out)
{
    int b = blockIdx.x;
    int tid = threadIdx.x;
    __shared__ __align__(16) float tps[HH];
    __shared__ float sc[PPG];
    tps[tid] = g_tp[b * HH + tid];
    __syncthreads();
    int warp = tid >> 5, lane = tid & 31;
    float4 tv = ((const float4*)tps)[lane];
    for (int p = warp; p < PPG; p += 4) {
        int node = pred[b * PPG + p];
        float4 hv = ((const float4*)h)[(size_t)node * 32 + lane];
        float d = hv.x * tv.x + hv.y * tv.y + hv.z * tv.z + hv.w * tv.w;
#pragma unroll
        for (int o = 16; o > 0; o >>= 1) d += __shfl_xor_sync(0xffffffffu, d, o);
        if (lane == 0) sc[p] = d + bbp[0];
    }
    __syncthreads();
    if (tid < 32) {
        float v = sc[tid];
        float m = v;
#pragma unroll
        for (int o = 16; o > 0; o >>= 1) m = fmaxf(m, __shfl_xor_sync(0xffffffffu, m, o));
        float e = expf(v - m);
        float s = e;
#pragma unroll
        for (int o = 16; o > 0; o >>= 1) s += __shfl_xor_sync(0xffffffffu, s, o);
        out[b * PPG + tid] = v - m - logf(s);
    }
}

// ---------------- launch ----------------
extern "C" void kernel_launch(void* const* d_in, const int* in_sizes, int n_in,
                              void* d_out, int out_size)
{
    (void)in_sizes; (void)n_in; (void)out_size;
    const float* emb_table = (const float*)d_in[0];
    const float* W_t       = (const float*)d_in[1];
    const float* b_t       = (const float*)d_in[2];
    const float* W_r       = (const float*)d_in[3];
    const float* b_r       = (const float*)d_in[4];
    const float* Wb        = (const float*)d_in[5];
    const float* bb        = (const float*)d_in[6];
    const float* norm      = (const float*)d_in[7];
    const int*   gid       = (const int*)d_in[8];
    const int*   spo       = (const int*)d_in[9];
    const int*   access_   = (const int*)d_in[10];
    const int*   pre       = (const int*)d_in[11];
    const int*   src       = (const int*)d_in[12];
    const int*   dst       = (const int*)d_in[13];
    const int*   etype     = (const int*)d_in[14];
    const int*   pred      = (const int*)d_in[15];
    float* out = (float*)d_out;

    void *p_cnt, *p_m, *p_emb, *p_h, *p_h2, *p_xinit;
    cudaGetSymbolAddress(&p_cnt,   g_cnt);
    cudaGetSymbolAddress(&p_m,     g_m);
    cudaGetSymbolAddress(&p_emb,   g_emb);
    cudaGetSymbolAddress(&p_h,     g_h);
    cudaGetSymbolAddress(&p_h2,    g_h2);
    cudaGetSymbolAddress(&p_xinit, g_xinit);

    const int TPB = 256;
    const int node_warp_blocks = NN / 8;
    const int gemm_blocks      = NN / 128;

    cudaFuncSetAttribute(k_gemm_tc, cudaFuncAttributeMaxDynamicSharedMemorySize, SM_TOT);
    cudaFuncSetAttribute(k_gemm_y,  cudaFuncAttributeMaxDynamicSharedMemorySize, SM_TOT);

    // --- CSR build ---
    cudaMemsetAsync(p_cnt, 0, (size_t)NN * sizeof(int), 0);
    k_count<<<EE / TPB, TPB>>>(dst);
    k_scan1<<<128, 256>>>();
    k_scan2<<<1, 128>>>();
    k_scan3<<<128, 256>>>();
    k_fill<<<EE / TPB, TPB>>>(src, dst, etype, norm);

    // --- init_forward + xinit ---
    k_init<<<node_warp_blocks, TPB>>>((const float4*)emb_table, gid, spo, access_, pre,
                                      W_t, b_t);

    // --- input projection ---
    k_gemm_tc<<<gemm_blocks, TPB, SM_TOT>>>((const float*)p_emb, W_t,
                                            (const float*)p_xinit, (float*)p_h);

    // --- layer 0 ---
    {
        dim3 grid(gemm_blocks, 4);
        k_gemm_y<<<grid, TPB, SM_TOT>>>((const float*)p_h, W_r, (float*)p_m);
    }
    k_gather_agg<<<node_warp_blocks, TPB>>>((const float*)p_m, b_r,
                                            (const float*)p_h, (float*)p_h2);

    // --- layer 1 ---
    {
        dim3 grid(gemm_blocks, 4);
        k_gemm_y<<<grid, TPB, SM_TOT>>>((const float*)p_h2, W_r + 4 * HH * HH, (float*)p_m);
    }
    k_gather_agg<<<node_warp_blocks, TPB>>>((const float*)p_m, b_r + HH,
                                            nullptr, (float*)p_h);

    // --- head ---
    k_transpose<<<(HH * HH) / TPB, TPB>>>(Wb);
    k_pool<<<BBG, HH>>>((const float*)p_h, pred);
    k_tp<<<BBG, HH>>>();
    k_score<<<BBG, HH>>>((const float*)p_h, pred, bb, out);
}

// round 8
// speedup vs baseline: 1.0633x; 1.0633x over previous
#include <cuda_runtime.h>
#include <cuda_bf16.h>
#include <cstdint>

#define NN   131072
#define EE   1048576
#define HH   128
#define BBG  512
#define PPG  32
#define NH   (NN*HH)

// ---------------- static device scratch ----------------
__device__ float g_emb[NH];
__device__ float g_h[NH];
__device__ float g_h2[NH];
__device__ float g_xinit[NH];
__device__ float g_m[4ULL * NH];   // per-type mailboxes m[t][N][128]
__device__ float g_pool[BBG * HH];
__device__ float g_tp[BBG * HH];
__device__ float g_wbt[HH * HH];
// dst-keyed CSR
__device__ int  g_cnt[NN];
__device__ int  g_off[NN + 1];
__device__ int  g_cur[NN];
__device__ int  g_bsum[128];
__device__ int2 g_rec[EE];         // {src | etype<<20, norm bits}

// ---------------- helpers ----------------
__device__ __forceinline__ uint32_t smem_u32(const void* p) {
    uint32_t a;
    asm("{ .reg .u64 t; cvta.to.shared.u64 t, %1; cvt.u32.u64 %0, t; }" : "=r"(a) : "l"(p));
    return a;
}
__device__ __forceinline__ void ldsm_x4(uint32_t r[4], uint32_t addr) {
    asm volatile("ldmatrix.sync.aligned.m8n8.x4.shared.b16 {%0,%1,%2,%3}, [%4];"
                 : "=r"(r[0]), "=r"(r[1]), "=r"(r[2]), "=r"(r[3]) : "r"(addr));
}
__device__ __forceinline__ void ldsm_x4_t(uint32_t r[4], uint32_t addr) {
    asm volatile("ldmatrix.sync.aligned.m8n8.x4.trans.shared.b16 {%0,%1,%2,%3}, [%4];"
                 : "=r"(r[0]), "=r"(r[1]), "=r"(r[2]), "=r"(r[3]) : "r"(addr));
}
__device__ __forceinline__ void mma_bf16(float* c, const uint32_t a[4], const uint32_t* b) {
    asm volatile(
        "mma.sync.aligned.m16n8k16.row.col.f32.bf16.bf16.f32 "
        "{%0,%1,%2,%3}, {%4,%5,%6,%7}, {%8,%9}, {%0,%1,%2,%3};"
        : "+f"(c[0]), "+f"(c[1]), "+f"(c[2]), "+f"(c[3])
        : "r"(a[0]), "r"(a[1]), "r"(a[2]), "r"(a[3]), "r"(b[0]), "r"(b[1]));
}
__device__ __forceinline__ void split2(float a, float b, uint32_t& hi, uint32_t& lo) {
    __nv_bfloat16 ha = __float2bfloat16_rn(a);
    __nv_bfloat16 hb = __float2bfloat16_rn(b);
    __nv_bfloat16 la = __float2bfloat16_rn(a - __bfloat162float(ha));
    __nv_bfloat16 lb = __float2bfloat16_rn(b - __bfloat162float(hb));
    hi = (uint32_t)__bfloat16_as_ushort(ha) | ((uint32_t)__bfloat16_as_ushort(hb) << 16);
    lo = (uint32_t)__bfloat16_as_ushort(la) | ((uint32_t)__bfloat16_as_ushort(lb) << 16);
}

// ---------------- CSR build (dst-keyed) ----------------
__global__ void k_count(const int* __restrict__ dst) {
    int e = blockIdx.x * blockDim.x + threadIdx.x;
    if (e >= EE) return;
    atomicAdd(&g_cnt[dst[e]], 1);
}

__global__ void k_scan1() {
    __shared__ int s[256];
    int t = threadIdx.x;
    int4 v = *(const int4*)(g_cnt + blockIdx.x * 1024 + t * 4);
    s[t] = v.x + v.y + v.z + v.w;
    __syncthreads();
    for (int o = 128; o > 0; o >>= 1) {
        if (t < o) s[t] += s[t + o];
        __syncthreads();
    }
    if (t == 0) g_bsum[blockIdx.x] = s[0];
}

__global__ void k_scan2() {
    __shared__ int s[128];
    int t = threadIdx.x;
    int mine = g_bsum[t];
    s[t] = mine;
    __syncthreads();
    for (int o = 1; o < 128; o <<= 1) {
        int add = (t >= o) ? s[t - o] : 0;
        __syncthreads();
        s[t] += add;
        __syncthreads();
    }
    g_bsum[t] = s[t] - mine;
}

__global__ void k_scan3() {
    __shared__ int s[256];
    int t = threadIdx.x;
    int base = blockIdx.x * 1024 + t * 4;
    int4 v = *(const int4*)(g_cnt + base);
    int tsum = v.x + v.y + v.z + v.w;
    s[t] = tsum;
    __syncthreads();
    for (int o = 1; o < 256; o <<= 1) {
        int add = (t >= o) ? s[t - o] : 0;
        __syncthreads();
        s[t] += add;
        __syncthreads();
    }
    int o0 = s[t] - tsum + g_bsum[blockIdx.x];
    int o1 = o0 + v.x, o2 = o1 + v.y, o3 = o2 + v.z;
    *(int4*)(g_off + base) = make_int4(o0, o1, o2, o3);
    *(int4*)(g_cur + base) = make_int4(o0, o1, o2, o3);
    if (base + 4 == NN) g_off[NN] = o3 + v.w;
}

__global__ void k_fill(const int* __restrict__ src, const int* __restrict__ dst,
                       const int* __restrict__ et,  const float* __restrict__ norm) {
    int e = blockIdx.x * blockDim.x + threadIdx.x;
    if (e >= EE) return;
    int p = atomicAdd(&g_cur[dst[e]], 1);
    g_rec[p] = make_int2(src[e] | (et[e] << 20), __float_as_int(norm[e]));
}

// ---------------- init_forward + xinit (warp per node, CSR) ----------------
__global__ void k_init(const float4* __restrict__ tab, const int* __restrict__ gid,
                       const int* __restrict__ spo, const int* __restrict__ acc_,
                       const int* __restrict__ pre, const float* __restrict__ Wt,
                       const float* __restrict__ bt)
{
    int node = (blockIdx.x * blockDim.x + threadIdx.x) >> 5;
    int lane = threadIdx.x & 31;
    if (node >= NN) return;
    int s0 = spo[node * 3 + 0];
    int s1 = spo[node * 3 + 1];
    int s2 = spo[node * 3 + 2];
    int beg = g_off[node], end = g_off[node + 1];

    float4 a = make_float4(0.f, 0.f, 0.f, 0.f);
    bool has_ne = false;
    for (int base = beg; base < end; base += 32) {
        int n = min(32, end - base);
        int2 r = (base + lane < end) ? g_rec[base + lane] : make_int2(-1, 0);
        for (int i = 0; i < n; i++) {
            int rx = __shfl_sync(0xffffffffu, r.x, i);
            int rn = __shfl_sync(0xffffffffu, r.y, i);
            if ((rx >> 20) != 0) continue;
            has_ne = true;
            int s = rx & 0xFFFFF;
            float nw = __int_as_float(rn);
            float4 hv = tab[(size_t)gid[s] * 32 + lane];
            a.x += hv.x * nw; a.y += hv.y * nw;
            a.z += hv.z * nw; a.w += hv.w * nw;
        }
    }
    float4 e4;
    if ((s0 + s2) > 0 && has_ne) e4 = a;
    else                         e4 = tab[(size_t)gid[node] * 32 + lane];
    ((float4*)g_emb)[(size_t)node * 32 + lane] = e4;

    float coef[5];
    coef[0] = (float)s0; coef[1] = (float)s1; coef[2] = (float)s2;
    coef[3] = (float)acc_[node]; coef[4] = (float)pre[node];
    float4 r = ((const float4*)bt)[lane];
#pragma unroll
    for (int j = 0; j < 5; j++) {
        float4 ww = ((const float4*)(Wt + (size_t)(128 + j) * HH))[lane];
        r.x += coef[j] * ww.x; r.y += coef[j] * ww.y;
        r.z += coef[j] * ww.z; r.w += coef[j] * ww.w;
    }
    ((float4*)g_xinit)[(size_t)node * 32 + lane] = r;
}

// ---------------- gather-first: all 4 per-type aggregates in one CSR pass ------
__global__ void k_gather4(const float* __restrict__ h, float* __restrict__ mail)
{
    int node = (blockIdx.x * blockDim.x + threadIdx.x) >> 5;
    int lane = threadIdx.x & 31;
    if (node >= NN) return;
    int beg = g_off[node], end = g_off[node + 1];

    float4 a0 = make_float4(0.f, 0.f, 0.f, 0.f);
    float4 a1 = a0, a2 = a0, a3 = a0;
    for (int base = beg; base < end; base += 32) {
        int n = min(32, end - base);
        int2 r = (base + lane < end) ? g_rec[base + lane] : make_int2(0, 0);
        for (int i = 0; i < n; i++) {
            int rx = __shfl_sync(0xffffffffu, r.x, i);
            int rn = __shfl_sync(0xffffffffu, r.y, i);
            int s = rx & 0xFFFFF;
            int t = rx >> 20;                  // warp-uniform
            float nw = __int_as_float(rn);
            float4 v = *(const float4*)(h + (size_t)s * HH + lane * 4);
            switch (t) {
            case 0: a0.x += v.x*nw; a0.y += v.y*nw; a0.z += v.z*nw; a0.w += v.w*nw; break;
            case 1: a1.x += v.x*nw; a1.y += v.y*nw; a1.z += v.z*nw; a1.w += v.w*nw; break;
            case 2: a2.x += v.x*nw; a2.y += v.y*nw; a2.z += v.z*nw; a2.w += v.w*nw; break;
            default:a3.x += v.x*nw; a3.y += v.y*nw; a3.z += v.z*nw; a3.w += v.w*nw; break;
            }
        }
    }
    size_t o = (size_t)node * 32 + lane;
    ((float4*)mail)[o]            = a0;
    ((float4*)mail)[o + NN * 32]  = a1;
    ((float4*)mail)[o + NN * 64]  = a2;
    ((float4*)mail)[o + NN * 96]  = a3;
}

// ---------------- HMMA GEMM core (occ 2, 64-wide K chunks) ----------------
#define SM_AHI 0
#define SM_ALO 18432
#define SM_BHI 36864
#define SM_BLO 54272
#define SM_TOT 71680

__device__ __forceinline__ void gemm_chunk_mma(uint32_t s0, int warp_m, int warp_n,
                                               int lane, float c[4][4][4]) {
#pragma unroll
    for (int ks = 0; ks < 4; ks++) {
        uint32_t ah[4][4], al[4][4];
#pragma unroll
        for (int mt = 0; mt < 4; mt++) {
            uint32_t row  = warp_m * 64 + mt * 16 + (lane & 15);
            uint32_t addr = s0 + SM_AHI + row * 144 + ks * 32 + ((lane >> 4) << 4);
            ldsm_x4(ah[mt], addr);
            ldsm_x4(al[mt], addr + (SM_ALO - SM_AHI));
        }
#pragma unroll
        for (int np = 0; np < 2; np++) {
            uint32_t kk   = ks * 16 + (lane & 15);
            uint32_t col  = warp_n * 32 + np * 16 + ((lane >> 4) & 1) * 8;
            uint32_t addr = s0 + SM_BHI + kk * 272 + col * 2;
            uint32_t bh[4], bl[4];
            ldsm_x4_t(bh, addr);
            ldsm_x4_t(bl, addr + (SM_BLO - SM_BHI));
#pragma unroll
            for (int mt = 0; mt < 4; mt++) {
                mma_bf16(c[mt][np * 2],     ah[mt], bh);
                mma_bf16(c[mt][np * 2],     al[mt], bh);
                mma_bf16(c[mt][np * 2],     ah[mt], bl);
                mma_bf16(c[mt][np * 2 + 1], ah[mt], bh + 2);
                mma_bf16(c[mt][np * 2 + 1], al[mt], bh + 2);
                mma_bf16(c[mt][np * 2 + 1], ah[mt], bl + 2);
            }
        }
    }
}

// load one 64-wide K chunk: ga = A-chunk base (row-major, HH stride), gb = B-chunk base
__device__ __forceinline__ void gemm_load_chunk(char* smem, int tid,
                                                const float* __restrict__ ga,
                                                const float* __restrict__ gb) {
    if (tid < 128) {
#pragma unroll
        for (int p = 0; p < 16; p++) {
            int e = p * 128 + tid;
            int r = e >> 4, c4 = e & 15;
            float4 v = *(const float4*)(ga + (size_t)r * HH + c4 * 4);
            uint32_t h0, l0, h1, l1;
            split2(v.x, v.y, h0, l0);
            split2(v.z, v.w, h1, l1);
            uint32_t off = (uint32_t)r * 144 + c4 * 8;
            *(uint2*)(smem + SM_AHI + off) = make_uint2(h0, h1);
            *(uint2*)(smem + SM_ALO + off) = make_uint2(l0, l1);
        }
    } else {
        int t = tid - 128;
#pragma unroll
        for (int p = 0; p < 16; p++) {
            int e = p * 128 + t;
            int k = e >> 5, c4 = e & 31;
            float4 v = *(const float4*)(gb + (size_t)k * HH + c4 * 4);
            uint32_t h0, l0, h1, l1;
            split2(v.x, v.y, h0, l0);
            split2(v.z, v.w, h1, l1);
            uint32_t off = (uint32_t)k * 272 + c4 * 8;
            *(uint2*)(smem + SM_BHI + off) = make_uint2(h0, h1);
            *(uint2*)(smem + SM_BLO + off) = make_uint2(l0, l1);
        }
    }
}

// input projection: C = A @ B (K=128) + Cadd
__global__ void __launch_bounds__(256, 2) k_gemm_tc(
    const float* __restrict__ A, const float* __restrict__ B,
    const float* __restrict__ Cadd, float* __restrict__ C)
{
    extern __shared__ char smem[];
    uint32_t s0 = smem_u32(smem);
    int tid = threadIdx.x, wid = tid >> 5, lane = tid & 31;
    int row0 = blockIdx.x * 128;
    int warp_m = wid & 1, warp_n = wid >> 1;

    float c[4][4][4];
#pragma unroll
    for (int i = 0; i < 4; i++)
#pragma unroll
        for (int j = 0; j < 4; j++)
#pragma unroll
            for (int q = 0; q < 4; q++) c[i][j][q] = 0.0f;

    for (int ch = 0; ch < 2; ch++) {
        gemm_load_chunk(smem, tid, A + (size_t)row0 * HH + ch * 64,
                        B + (size_t)(ch * 64) * HH);
        __syncthreads();
        gemm_chunk_mma(s0, warp_m, warp_n, lane, c);
        __syncthreads();
    }

#pragma unroll
    for (int mt = 0; mt < 4; mt++) {
#pragma unroll
        for (int nt = 0; nt < 4; nt++) {
            int col = warp_n * 32 + nt * 8 + (lane & 3) * 2;
#pragma unroll
            for (int half = 0; half < 2; half++) {
                long row  = row0 + warp_m * 64 + mt * 16 + (lane >> 2) + half * 8;
                long base = row * HH + col;
                float2 v;
                v.x = c[mt][nt][half * 2 + 0];
                v.y = c[mt][nt][half * 2 + 1];
                float2 t = *(const float2*)(Cadd + base);
                v.x += t.x; v.y += t.y;
                *(float2*)(C + base) = v;
            }
        }
    }
}

// layer GEMM: C = relu(sum_t mail_t @ W_t + bias) (+resid);  K = 512 over 8 chunks
__global__ void __launch_bounds__(256, 2) k_gemm_l(
    const float* __restrict__ mail, const float* __restrict__ Wl,
    const float* __restrict__ bias, const float* __restrict__ resid,
    float* __restrict__ C)
{
    extern __shared__ char smem[];
    uint32_t s0 = smem_u32(smem);
    int tid = threadIdx.x, wid = tid >> 5, lane = tid & 31;
    int row0 = blockIdx.x * 128;
    int warp_m = wid & 1, warp_n = wid >> 1;

    float c[4][4][4];
#pragma unroll
    for (int i = 0; i < 4; i++)
#pragma unroll
        for (int j = 0; j < 4; j++)
#pragma unroll
            for (int q = 0; q < 4; q++) c[i][j][q] = 0.0f;

    for (int ch = 0; ch < 8; ch++) {
        int t   = ch >> 1;
        int sub = ch & 1;
        gemm_load_chunk(smem, tid,
                        mail + (size_t)t * NH + (size_t)row0 * HH + sub * 64,
                        Wl + (size_t)t * HH * HH + (size_t)(sub * 64) * HH);
        __syncthreads();
        gemm_chunk_mma(s0, warp_m, warp_n, lane, c);
        __syncthreads();
    }

#pragma unroll
    for (int mt = 0; mt < 4; mt++) {
#pragma unroll
        for (int nt = 0; nt < 4; nt++) {
            int col = warp_n * 32 + nt * 8 + (lane & 3) * 2;
            float2 bv = *(const float2*)(bias + col);
#pragma unroll
            for (int half = 0; half < 2; half++) {
                long row  = row0 + warp_m * 64 + mt * 16 + (lane >> 2) + half * 8;
                long base = row * HH + col;
                float2 v;
                v.x = fmaxf(c[mt][nt][half * 2 + 0] + bv.x, 0.f);
                v.y = fmaxf(c[mt][nt][half * 2 + 1] + bv.y, 0.f);
                if (resid) {
                    float2 rr = *(const float2*)(resid + base);
                    v.x += rr.x; v.y += rr.y;
                }
                *(float2*)(C + base) = v;
            }
        }
    }
}

// ---------------- head kernels ----------------
__global__ void k_transpose(const float* __restrict__ Wb) {
    int idx = blockIdx.x * blockDim.x + threadIdx.x;
    if (idx >= HH * HH) return;
    int r = idx >> 7, c = idx & 127;
    g_wbt[c * HH + r] = Wb[idx];
}

__global__ void k_pool(const float* __restrict__ h, const int* __restrict__ pred) {
    int b = blockIdx.x, j = threadIdx.x;
    float acc = 0.0f;
#pragma unroll 4
    for (int p = 0; p < PPG; p++) {
        int node = pred[b * PPG + p];
        acc += h[(size_t)node * HH + j];
    }
    g_pool[b * HH + j] = acc * (1.0f / PPG);
}

__global__ void k_tp() {
    int b = blockIdx.x, hrow = threadIdx.x;
    __shared__ float ps[HH];
    ps[hrow] = g_pool[b * HH + hrow];
    __syncthreads();
    float acc = 0.0f;
#pragma unroll 8
    for (int k = 0; k < HH; k++)
        acc += g_wbt[(size_t)k * HH + hrow] * ps[k];
    g_tp[b * HH + hrow] = acc;
}

__global__ void k_score(const float* __restrict__ h, const int* __restrict__ pred,
                        const float* __restrict__ bbp, float* __restrict__ out)
{
    int b = blockIdx.x;
    int tid = threadIdx.x;
    __shared__ __align__(16) float tps[HH];
    __shared__ float sc[PPG];
    tps[tid] = g_tp[b * HH + tid];
    __syncthreads();
    int warp = tid >> 5, lane = tid & 31;
    float4 tv = ((const float4*)tps)[lane];
    for (int p = warp; p < PPG; p += 4) {
        int node = pred[b * PPG + p];
        float4 hv = ((const float4*)h)[(size_t)node * 32 + lane];
        float d = hv.x * tv.x + hv.y * tv.y + hv.z * tv.z + hv.w * tv.w;
#pragma unroll
        for (int o = 16; o > 0; o >>= 1) d += __shfl_xor_sync(0xffffffffu, d, o);
        if (lane == 0) sc[p] = d + bbp[0];
    }
    __syncthreads();
    if (tid < 32) {
        float v = sc[tid];
        float m = v;
#pragma unroll
        for (int o = 16; o > 0; o >>= 1) m = fmaxf(m, __shfl_xor_sync(0xffffffffu, m, o));
        float e = expf(v - m);
        float s = e;
#pragma unroll
        for (int o = 16; o > 0; o >>= 1) s += __shfl_xor_sync(0xffffffffu, s, o);
        out[b * PPG + tid] = v - m - logf(s);
    }
}

// ---------------- launch ----------------
extern "C" void kernel_launch(void* const* d_in, const int* in_sizes, int n_in,
                              void* d_out, int out_size)
{
    (void)in_sizes; (void)n_in; (void)out_size;
    const float* emb_table = (const float*)d_in[0];
    const float* W_t       = (const float*)d_in[1];
    const float* b_t       = (const float*)d_in[2];
    const float* W_r       = (const float*)d_in[3];
    const float* b_r       = (const float*)d_in[4];
    const float* Wb        = (const float*)d_in[5];
    const float* bb        = (const float*)d_in[6];
    const float* norm      = (const float*)d_in[7];
    const int*   gid       = (const int*)d_in[8];
    const int*   spo       = (const int*)d_in[9];
    const int*   access_   = (const int*)d_in[10];
    const int*   pre       = (const int*)d_in[11];
    const int*   src       = (const int*)d_in[12];
    const int*   dst       = (const int*)d_in[13];
    const int*   etype     = (const int*)d_in[14];
    const int*   pred      = (const int*)d_in[15];
    float* out = (float*)d_out;

    void *p_cnt, *p_m, *p_emb, *p_h, *p_h2, *p_xinit;
    cudaGetSymbolAddress(&p_cnt,   g_cnt);
    cudaGetSymbolAddress(&p_m,     g_m);
    cudaGetSymbolAddress(&p_emb,   g_emb);
    cudaGetSymbolAddress(&p_h,     g_h);
    cudaGetSymbolAddress(&p_h2,    g_h2);
    cudaGetSymbolAddress(&p_xinit, g_xinit);

    const int TPB = 256;
    const int node_warp_blocks = NN / 8;
    const int gemm_blocks      = NN / 128;

    cudaFuncSetAttribute(k_gemm_tc, cudaFuncAttributeMaxDynamicSharedMemorySize, SM_TOT);
    cudaFuncSetAttribute(k_gemm_l,  cudaFuncAttributeMaxDynamicSharedMemorySize, SM_TOT);

    // --- CSR build ---
    cudaMemsetAsync(p_cnt, 0, (size_t)NN * sizeof(int), 0);
    k_count<<<EE / TPB, TPB>>>(dst);
    k_scan1<<<128, 256>>>();
    k_scan2<<<1, 128>>>();
    k_scan3<<<128, 256>>>();
    k_fill<<<EE / TPB, TPB>>>(src, dst, etype, norm);

    // --- init_forward + xinit ---
    k_init<<<node_warp_blocks, TPB>>>((const float4*)emb_table, gid, spo, access_, pre,
                                      W_t, b_t);

    // --- input projection ---
    k_gemm_tc<<<gemm_blocks, TPB, SM_TOT>>>((const float*)p_emb, W_t,
                                            (const float*)p_xinit, (float*)p_h);

    // --- layer 0: gather-first ---
    k_gather4<<<node_warp_blocks, TPB>>>((const float*)p_h, (float*)p_m);
    k_gemm_l<<<gemm_blocks, TPB, SM_TOT>>>((const float*)p_m, W_r,
                                           b_r, (const float*)p_h, (float*)p_h2);

    // --- layer 1 ---
    k_gather4<<<node_warp_blocks, TPB>>>((const float*)p_h2, (float*)p_m);
    k_gemm_l<<<gemm_blocks, TPB, SM_TOT>>>((const float*)p_m, W_r + 4 * HH * HH,
                                           b_r + HH, nullptr, (float*)p_h);

    // --- head ---
    k_transpose<<<(HH * HH) / TPB, TPB>>>(Wb);
    k_pool<<<BBG, HH>>>((const float*)p_h, pred);
    k_tp<<<BBG, HH>>>();
    k_score<<<BBG, HH>>>((const float*)p_h, pred, bb, out);
}

// round 9
// speedup vs baseline: 1.1640x; 1.0947x over previous
#include <cuda_runtime.h>
#include <cuda_bf16.h>
#include <cstdint>

#define NN   131072
#define EE   1048576
#define HH   128
#define BBG  512
#define PPG  32
#define NH   (NN*HH)

// ---------------- static device scratch ----------------
__device__ float g_emb[NH];
__device__ float g_h[NH];
__device__ float g_h2[NH];
__device__ uint16_t g_mh[4ULL * NH];   // mailbox hi (bf16)
__device__ uint16_t g_ml[4ULL * NH];   // mailbox lo (bf16)
__device__ uint16_t g_wh[2 * 4 * HH * HH];  // W_r hi
__device__ uint16_t g_wl[2 * 4 * HH * HH];  // W_r lo
__device__ float g_pool[BBG * HH];
__device__ float g_tp[BBG * HH];
__device__ float g_wbt[HH * HH];
// dst-keyed CSR
__device__ int  g_cnt[NN];
__device__ int  g_off[NN + 1];
__device__ int  g_cur[NN];
__device__ int  g_bsum[128];
__device__ int2 g_rec[EE];             // {src | etype<<20, norm bits}

// ---------------- helpers ----------------
__device__ __forceinline__ uint32_t smem_u32(const void* p) {
    uint32_t a;
    asm("{ .reg .u64 t; cvta.to.shared.u64 t, %1; cvt.u32.u64 %0, t; }" : "=r"(a) : "l"(p));
    return a;
}
__device__ __forceinline__ void ldsm_x4(uint32_t r[4], uint32_t addr) {
    asm volatile("ldmatrix.sync.aligned.m8n8.x4.shared.b16 {%0,%1,%2,%3}, [%4];"
                 : "=r"(r[0]), "=r"(r[1]), "=r"(r[2]), "=r"(r[3]) : "r"(addr));
}
__device__ __forceinline__ void ldsm_x4_t(uint32_t r[4], uint32_t addr) {
    asm volatile("ldmatrix.sync.aligned.m8n8.x4.trans.shared.b16 {%0,%1,%2,%3}, [%4];"
                 : "=r"(r[0]), "=r"(r[1]), "=r"(r[2]), "=r"(r[3]) : "r"(addr));
}
__device__ __forceinline__ void mma_bf16(float* c, const uint32_t a[4], const uint32_t* b) {
    asm volatile(
        "mma.sync.aligned.m16n8k16.row.col.f32.bf16.bf16.f32 "
        "{%0,%1,%2,%3}, {%4,%5,%6,%7}, {%8,%9}, {%0,%1,%2,%3};"
        : "+f"(c[0]), "+f"(c[1]), "+f"(c[2]), "+f"(c[3])
        : "r"(a[0]), "r"(a[1]), "r"(a[2]), "r"(a[3]), "r"(b[0]), "r"(b[1]));
}
__device__ __forceinline__ void split2(float a, float b, uint32_t& hi, uint32_t& lo) {
    __nv_bfloat16 ha = __float2bfloat16_rn(a);
    __nv_bfloat16 hb = __float2bfloat16_rn(b);
    __nv_bfloat16 la = __float2bfloat16_rn(a - __bfloat162float(ha));
    __nv_bfloat16 lb = __float2bfloat16_rn(b - __bfloat162float(hb));
    hi = (uint32_t)__bfloat16_as_ushort(ha) | ((uint32_t)__bfloat16_as_ushort(hb) << 16);
    lo = (uint32_t)__bfloat16_as_ushort(la) | ((uint32_t)__bfloat16_as_ushort(lb) << 16);
}
__device__ __forceinline__ void cp16(uint32_t smem, const void* g) {
    asm volatile("cp.async.cg.shared.global [%0], [%1], 16;" :: "r"(smem), "l"(g));
}

// ---------------- CSR build (dst-keyed) ----------------
__global__ void k_count(const int* __restrict__ dst) {
    int e = blockIdx.x * blockDim.x + threadIdx.x;
    if (e >= EE) return;
    atomicAdd(&g_cnt[dst[e]], 1);
}

__global__ void k_scan1() {
    __shared__ int s[256];
    int t = threadIdx.x;
    int4 v = *(const int4*)(g_cnt + blockIdx.x * 1024 + t * 4);
    s[t] = v.x + v.y + v.z + v.w;
    __syncthreads();
    for (int o = 128; o > 0; o >>= 1) {
        if (t < o) s[t] += s[t + o];
        __syncthreads();
    }
    if (t == 0) g_bsum[blockIdx.x] = s[0];
}

__global__ void k_scan2() {
    __shared__ int s[128];
    int t = threadIdx.x;
    int mine = g_bsum[t];
    s[t] = mine;
    __syncthreads();
    for (int o = 1; o < 128; o <<= 1) {
        int add = (t >= o) ? s[t - o] : 0;
        __syncthreads();
        s[t] += add;
        __syncthreads();
    }
    g_bsum[t] = s[t] - mine;
}

__global__ void k_scan3() {
    __shared__ int s[256];
    int t = threadIdx.x;
    int base = blockIdx.x * 1024 + t * 4;
    int4 v = *(const int4*)(g_cnt + base);
    int tsum = v.x + v.y + v.z + v.w;
    s[t] = tsum;
    __syncthreads();
    for (int o = 1; o < 256; o <<= 1) {
        int add = (t >= o) ? s[t - o] : 0;
        __syncthreads();
        s[t] += add;
        __syncthreads();
    }
    int o0 = s[t] - tsum + g_bsum[blockIdx.x];
    int o1 = o0 + v.x, o2 = o1 + v.y, o3 = o2 + v.z;
    *(int4*)(g_off + base) = make_int4(o0, o1, o2, o3);
    *(int4*)(g_cur + base) = make_int4(o0, o1, o2, o3);
    if (base + 4 == NN) g_off[NN] = o3 + v.w;
}

__global__ void k_fill(const int* __restrict__ src, const int* __restrict__ dst,
                       const int* __restrict__ et,  const float* __restrict__ norm) {
    int e = blockIdx.x * blockDim.x + threadIdx.x;
    if (e >= EE) return;
    int p = atomicAdd(&g_cur[dst[e]], 1);
    g_rec[p] = make_int2(src[e] | (et[e] << 20), __float_as_int(norm[e]));
}

// ---------------- weight split ----------------
__global__ void k_wsplit(const float* __restrict__ Wr) {
    int i = blockIdx.x * blockDim.x + threadIdx.x;   // 131072
    float v = Wr[i];
    __nv_bfloat16 h = __float2bfloat16_rn(v);
    g_wh[i] = __bfloat16_as_ushort(h);
    g_wl[i] = __bfloat16_as_ushort(__float2bfloat16_rn(v - __bfloat162float(h)));
}

// ---------------- init_forward (warp per node, CSR) ----------------
__global__ void k_init(const float4* __restrict__ tab, const int* __restrict__ gid,
                       const int* __restrict__ spo)
{
    int node = (blockIdx.x * blockDim.x + threadIdx.x) >> 5;
    int lane = threadIdx.x & 31;
    if (node >= NN) return;
    int s0 = spo[node * 3 + 0];
    int s2 = spo[node * 3 + 2];
    int beg = g_off[node], end = g_off[node + 1];

    float4 a = make_float4(0.f, 0.f, 0.f, 0.f);
    bool has_ne = false;
    for (int base = beg; base < end; base += 32) {
        int n = min(32, end - base);
        int2 r = (base + lane < end) ? g_rec[base + lane] : make_int2(-1, 0);
        for (int i = 0; i < n; i++) {
            int rx = __shfl_sync(0xffffffffu, r.x, i);
            int rn = __shfl_sync(0xffffffffu, r.y, i);
            if ((rx >> 20) != 0) continue;
            has_ne = true;
            int s = rx & 0xFFFFF;
            float nw = __int_as_float(rn);
            float4 hv = tab[(size_t)gid[s] * 32 + lane];
            a.x += hv.x * nw; a.y += hv.y * nw;
            a.z += hv.z * nw; a.w += hv.w * nw;
        }
    }
    float4 e4;
    if ((s0 + s2) > 0 && has_ne) e4 = a;
    else                         e4 = tab[(size_t)gid[node] * 32 + lane];
    ((float4*)g_emb)[(size_t)node * 32 + lane] = e4;
}

// ---------------- gather-first: 4 per-type aggregates, bf16 hi/lo out ------
__global__ void k_gather4(const float* __restrict__ h)
{
    int node = (blockIdx.x * blockDim.x + threadIdx.x) >> 5;
    int lane = threadIdx.x & 31;
    if (node >= NN) return;
    int beg = g_off[node], end = g_off[node + 1];

    float4 a0 = make_float4(0.f, 0.f, 0.f, 0.f);
    float4 a1 = a0, a2 = a0, a3 = a0;
    for (int base = beg; base < end; base += 32) {
        int n = min(32, end - base);
        int2 r = (base + lane < end) ? g_rec[base + lane] : make_int2(0, 0);
        for (int i = 0; i < n; i++) {
            int rx = __shfl_sync(0xffffffffu, r.x, i);
            int rn = __shfl_sync(0xffffffffu, r.y, i);
            int s = rx & 0xFFFFF;
            int t = rx >> 20;
            float nw = __int_as_float(rn);
            float4 v = *(const float4*)(h + (size_t)s * HH + lane * 4);
            switch (t) {
            case 0: a0.x += v.x*nw; a0.y += v.y*nw; a0.z += v.z*nw; a0.w += v.w*nw; break;
            case 1: a1.x += v.x*nw; a1.y += v.y*nw; a1.z += v.z*nw; a1.w += v.w*nw; break;
            case 2: a2.x += v.x*nw; a2.y += v.y*nw; a2.z += v.z*nw; a2.w += v.w*nw; break;
            default:a3.x += v.x*nw; a3.y += v.y*nw; a3.z += v.z*nw; a3.w += v.w*nw; break;
            }
        }
    }
    size_t o = (size_t)node * 32 + lane;
    float4 acc[4] = {a0, a1, a2, a3};
#pragma unroll
    for (int t = 0; t < 4; t++) {
        uint32_t h0, l0, h1, l1;
        split2(acc[t].x, acc[t].y, h0, l0);
        split2(acc[t].z, acc[t].w, h1, l1);
        ((uint2*)(g_mh + (size_t)t * NH))[o] = make_uint2(h0, h1);
        ((uint2*)(g_ml + (size_t)t * NH))[o] = make_uint2(l0, l1);
    }
}

// ---------------- fp32 HMMA GEMM (input projection) ----------------
#define SM_AHI 0
#define SM_ALO 18432
#define SM_BHI 36864
#define SM_BLO 54272
#define SM_TOT 71680

__global__ void __launch_bounds__(256, 2) k_gemm_tc(
    const float* __restrict__ A, const float* __restrict__ Wt,
    const int* __restrict__ spo, const int* __restrict__ acc_,
    const int* __restrict__ pre, const float* __restrict__ bt,
    float* __restrict__ C)
{
    extern __shared__ char smem[];
    uint32_t s0 = smem_u32(smem);
    int tid = threadIdx.x, wid = tid >> 5, lane = tid & 31;
    int row0 = blockIdx.x * 128;
    int warp_m = wid & 1, warp_n = wid >> 1;

    float c[4][4][4];
#pragma unroll
    for (int i = 0; i < 4; i++)
#pragma unroll
        for (int j = 0; j < 4; j++)
#pragma unroll
            for (int q = 0; q < 4; q++) c[i][j][q] = 0.0f;

    for (int ch = 0; ch < 2; ch++) {
        // load + split chunk
        if (tid < 128) {
            const float* ga = A + (size_t)row0 * HH + ch * 64;
#pragma unroll
            for (int p = 0; p < 16; p++) {
                int e = p * 128 + tid;
                int r = e >> 4, c4 = e & 15;
                float4 v = *(const float4*)(ga + (size_t)r * HH + c4 * 4);
                uint32_t h0, l0, h1, l1;
                split2(v.x, v.y, h0, l0);
                split2(v.z, v.w, h1, l1);
                uint32_t off = (uint32_t)r * 144 + c4 * 8;
                *(uint2*)(smem + SM_AHI + off) = make_uint2(h0, h1);
                *(uint2*)(smem + SM_ALO + off) = make_uint2(l0, l1);
            }
        } else {
            int t = tid - 128;
            const float* gb = Wt + (size_t)(ch * 64) * HH;
#pragma unroll
            for (int p = 0; p < 16; p++) {
                int e = p * 128 + t;
                int k = e >> 5, c4 = e & 31;
                float4 v = *(const float4*)(gb + (size_t)k * HH + c4 * 4);
                uint32_t h0, l0, h1, l1;
                split2(v.x, v.y, h0, l0);
                split2(v.z, v.w, h1, l1);
                uint32_t off = (uint32_t)k * 272 + c4 * 8;
                *(uint2*)(smem + SM_BHI + off) = make_uint2(h0, h1);
                *(uint2*)(smem + SM_BLO + off) = make_uint2(l0, l1);
            }
        }
        __syncthreads();

#pragma unroll
        for (int ks = 0; ks < 4; ks++) {
            uint32_t ah[4][4], al[4][4];
#pragma unroll
            for (int mt = 0; mt < 4; mt++) {
                uint32_t row  = warp_m * 64 + mt * 16 + (lane & 15);
                uint32_t addr = s0 + SM_AHI + row * 144 + ks * 32 + ((lane >> 4) << 4);
                ldsm_x4(ah[mt], addr);
                ldsm_x4(al[mt], addr + (SM_ALO - SM_AHI));
            }
#pragma unroll
            for (int np = 0; np < 2; np++) {
                uint32_t kk   = ks * 16 + (lane & 15);
                uint32_t col  = warp_n * 32 + np * 16 + ((lane >> 4) & 1) * 8;
                uint32_t addr = s0 + SM_BHI + kk * 272 + col * 2;
                uint32_t bh[4], bl[4];
                ldsm_x4_t(bh, addr);
                ldsm_x4_t(bl, addr + (SM_BLO - SM_BHI));
#pragma unroll
                for (int mt = 0; mt < 4; mt++) {
                    mma_bf16(c[mt][np * 2],     ah[mt], bh);
                    mma_bf16(c[mt][np * 2],     al[mt], bh);
                    mma_bf16(c[mt][np * 2],     ah[mt], bl);
                    mma_bf16(c[mt][np * 2 + 1], ah[mt], bh + 2);
                    mma_bf16(c[mt][np * 2 + 1], al[mt], bh + 2);
                    mma_bf16(c[mt][np * 2 + 1], ah[mt], bl + 2);
                }
            }
        }
        __syncthreads();
    }

    // stage Wt tail rows (5 x 128) + bt into smem
    float* sw = (float*)smem;
    for (int i = tid; i < 768; i += 256)
        sw[i] = (i < 640) ? Wt[(size_t)(128 + (i >> 7)) * HH + (i & 127)] : bt[i - 640];
    __syncthreads();

    // epilogue: C = mma + xinit(row-features)
#pragma unroll
    for (int mt = 0; mt < 4; mt++) {
#pragma unroll
        for (int half = 0; half < 2; half++) {
            long row = row0 + warp_m * 64 + mt * 16 + (lane >> 2) + half * 8;
            float cf0 = (float)spo[row * 3 + 0];
            float cf1 = (float)spo[row * 3 + 1];
            float cf2 = (float)spo[row * 3 + 2];
            float cf3 = (float)acc_[row];
            float cf4 = (float)pre[row];
#pragma unroll
            for (int nt = 0; nt < 4; nt++) {
                int col = warp_n * 32 + nt * 8 + (lane & 3) * 2;
                float2 v;
                v.x = c[mt][nt][half * 2 + 0];
                v.y = c[mt][nt][half * 2 + 1];
                v.x += sw[640 + col]     + cf0 * sw[col]       + cf1 * sw[128 + col]
                     + cf2 * sw[256 + col] + cf3 * sw[384 + col] + cf4 * sw[512 + col];
                v.y += sw[641 + col]     + cf0 * sw[col + 1]   + cf1 * sw[129 + col]
                     + cf2 * sw[257 + col] + cf3 * sw[385 + col] + cf4 * sw[513 + col];
                *(float2*)(C + row * HH + col) = v;
            }
        }
    }
}

// ---------------- layer GEMM: cp.async double-buffered, K=512 over 16 chunks ----
#define GL_AHI 0
#define GL_ALO 10240
#define GL_BHI 20480
#define GL_BLO 29184
#define GL_BUF 37888
#define GL_TOT 75776

__global__ void __launch_bounds__(256, 2) k_gemm_l(
    const uint16_t* __restrict__ mh, const uint16_t* __restrict__ ml,
    const uint16_t* __restrict__ wh, const uint16_t* __restrict__ wl,
    const float* __restrict__ bias, const float* __restrict__ resid,
    float* __restrict__ C)
{
    extern __shared__ char smem[];
    uint32_t s0 = smem_u32(smem);
    int tid = threadIdx.x, wid = tid >> 5, lane = tid & 31;
    int row0 = blockIdx.x * 128;
    int warp_m = wid & 1, warp_n = wid >> 1;

    float c[4][4][4];
#pragma unroll
    for (int i = 0; i < 4; i++)
#pragma unroll
        for (int j = 0; j < 4; j++)
#pragma unroll
            for (int q = 0; q < 4; q++) c[i][j][q] = 0.0f;

    // cp.async loader for one chunk (t = ch>>2, sub = ch&3)
    auto load_chunk = [&](int ch, int buf) {
        int t = ch >> 2, sub = ch & 3;
        const uint16_t* mhb = mh + (size_t)t * NH + (size_t)row0 * HH + sub * 32;
        const uint16_t* mlb = ml + (size_t)t * NH + (size_t)row0 * HH + sub * 32;
        const uint16_t* whb = wh + (size_t)t * HH * HH + (size_t)(sub * 32) * HH;
        const uint16_t* wlb = wl + (size_t)t * HH * HH + (size_t)(sub * 32) * HH;
        uint32_t sb = s0 + buf * GL_BUF;
#pragma unroll
        for (int q = 0; q < 2; q++) {     // A: 512 segs hi + 512 lo
            int s = q * 256 + tid;
            int r = s >> 2, part = s & 3;
            cp16(sb + GL_AHI + r * 80 + part * 16, mhb + (size_t)r * HH + part * 8);
            cp16(sb + GL_ALO + r * 80 + part * 16, mlb + (size_t)r * HH + part * 8);
        }
#pragma unroll
        for (int q = 0; q < 2; q++) {     // B: 512 segs hi + 512 lo
            int s = q * 256 + tid;
            int r = s >> 4, part = s & 15;
            cp16(sb + GL_BHI + r * 272 + part * 16, whb + (size_t)r * HH + part * 8);
            cp16(sb + GL_BLO + r * 272 + part * 16, wlb + (size_t)r * HH + part * 8);
        }
    };

    load_chunk(0, 0);
    asm volatile("cp.async.commit_group;" ::: "memory");

    for (int ch = 0; ch < 16; ch++) {
        if (ch + 1 < 16) {
            load_chunk(ch + 1, (ch + 1) & 1);
            asm volatile("cp.async.commit_group;" ::: "memory");
            asm volatile("cp.async.wait_group 1;" ::: "memory");
        } else {
            asm volatile("cp.async.wait_group 0;" ::: "memory");
        }
        __syncthreads();

        uint32_t sb = s0 + (ch & 1) * GL_BUF;
#pragma unroll
        for (int ks = 0; ks < 2; ks++) {
            uint32_t ah[4][4], al[4][4];
#pragma unroll
            for (int mt = 0; mt < 4; mt++) {
                uint32_t row  = warp_m * 64 + mt * 16 + (lane & 15);
                uint32_t addr = sb + GL_AHI + row * 80 + ks * 32 + ((lane >> 4) << 4);
                ldsm_x4(ah[mt], addr);
                ldsm_x4(al[mt], addr + (GL_ALO - GL_AHI));
            }
#pragma unroll
            for (int np = 0; np < 2; np++) {
                uint32_t kk   = ks * 16 + (lane & 15);
                uint32_t col  = warp_n * 32 + np * 16 + ((lane >> 4) & 1) * 8;
                uint32_t addr = sb + GL_BHI + kk * 272 + col * 2;
                uint32_t bh[4], bl[4];
                ldsm_x4_t(bh, addr);
                ldsm_x4_t(bl, addr + (GL_BLO - GL_BHI));
#pragma unroll
                for (int mt = 0; mt < 4; mt++) {
                    mma_bf16(c[mt][np * 2],     ah[mt], bh);
                    mma_bf16(c[mt][np * 2],     al[mt], bh);
                    mma_bf16(c[mt][np * 2],     ah[mt], bl);
                    mma_bf16(c[mt][np * 2 + 1], ah[mt], bh + 2);
                    mma_bf16(c[mt][np * 2 + 1], al[mt], bh + 2);
                    mma_bf16(c[mt][np * 2 + 1], ah[mt], bl + 2);
                }
            }
        }
        __syncthreads();
    }

#pragma unroll
    for (int mt = 0; mt < 4; mt++) {
#pragma unroll
        for (int nt = 0; nt < 4; nt++) {
            int col = warp_n * 32 + nt * 8 + (lane & 3) * 2;
            float2 bv = *(const float2*)(bias + col);
#pragma unroll
            for (int half = 0; half < 2; half++) {
                long row  = row0 + warp_m * 64 + mt * 16 + (lane >> 2) + half * 8;
                long base = row * HH + col;
                float2 v;
                v.x = fmaxf(c[mt][nt][half * 2 + 0] + bv.x, 0.f);
                v.y = fmaxf(c[mt][nt][half * 2 + 1] + bv.y, 0.f);
                if (resid) {
                    float2 rr = *(const float2*)(resid + base);
                    v.x += rr.x; v.y += rr.y;
                }
                *(float2*)(C + base) = v;
            }
        }
    }
}

// ---------------- head kernels ----------------
__global__ void k_transpose(const float* __restrict__ Wb) {
    int idx = blockIdx.x * blockDim.x + threadIdx.x;
    if (idx >= HH * HH) return;
    int r = idx >> 7, c = idx & 127;
    g_wbt[c * HH + r] = Wb[idx];
}

__global__ void k_pool(const float* __restrict__ h, const int* __restrict__ pred) {
    int b = blockIdx.x, j = threadIdx.x;
    float acc = 0.0f;
#pragma unroll 4
    for (int p = 0; p < PPG; p++) {
        int node = pred[b * PPG + p];
        acc += h[(size_t)node * HH + j];
    }
    g_pool[b * HH + j] = acc * (1.0f / PPG);
}

__global__ void k_tp() {
    int b = blockIdx.x, hrow = threadIdx.x;
    __shared__ float ps[HH];
    ps[hrow] = g_pool[b * HH + hrow];
    __syncthreads();
    float acc = 0.0f;
#pragma unroll 8
    for (int k = 0; k < HH; k++)
        acc += g_wbt[(size_t)k * HH + hrow] * ps[k];
    g_tp[b * HH + hrow] = acc;
}

__global__ void k_score(const float* __restrict__ h, const int* __restrict__ pred,
                        const float* __restrict__ bbp, float* __restrict__ out)
{
    int b = blockIdx.x;
    int tid = threadIdx.x;
    __shared__ __align__(16) float tps[HH];
    __shared__ float sc[PPG];
    tps[tid] = g_tp[b * HH + tid];
    __syncthreads();
    int warp = tid >> 5, lane = tid & 31;
    float4 tv = ((const float4*)tps)[lane];
    for (int p = warp; p < PPG; p += 4) {
        int node = pred[b * PPG + p];
        float4 hv = ((const float4*)h)[(size_t)node * 32 + lane];
        float d = hv.x * tv.x + hv.y * tv.y + hv.z * tv.z + hv.w * tv.w;
#pragma unroll
        for (int o = 16; o > 0; o >>= 1) d += __shfl_xor_sync(0xffffffffu, d, o);
        if (lane == 0) sc[p] = d + bbp[0];
    }
    __syncthreads();
    if (tid < 32) {
        float v = sc[tid];
        float m = v;
#pragma unroll
        for (int o = 16; o > 0; o >>= 1) m = fmaxf(m, __shfl_xor_sync(0xffffffffu, m, o));
        float e = expf(v - m);
        float s = e;
#pragma unroll
        for (int o = 16; o > 0; o >>= 1) s += __shfl_xor_sync(0xffffffffu, s, o);
        out[b * PPG + tid] = v - m - logf(s);
    }
}

// ---------------- launch ----------------
extern "C" void kernel_launch(void* const* d_in, const int* in_sizes, int n_in,
                              void* d_out, int out_size)
{
    (void)in_sizes; (void)n_in; (void)out_size;
    const float* emb_table = (const float*)d_in[0];
    const float* W_t       = (const float*)d_in[1];
    const float* b_t       = (const float*)d_in[2];
    const float* W_r       = (const float*)d_in[3];
    const float* b_r       = (const float*)d_in[4];
    const float* Wb        = (const float*)d_in[5];
    const float* bb        = (const float*)d_in[6];
    const float* norm      = (const float*)d_in[7];
    const int*   gid       = (const int*)d_in[8];
    const int*   spo       = (const int*)d_in[9];
    const int*   access_   = (const int*)d_in[10];
    const int*   pre       = (const int*)d_in[11];
    const int*   src       = (const int*)d_in[12];
    const int*   dst       = (const int*)d_in[13];
    const int*   etype     = (const int*)d_in[14];
    const int*   pred      = (const int*)d_in[15];
    float* out = (float*)d_out;

    void *p_cnt, *p_emb, *p_h, *p_h2, *p_mh, *p_ml, *p_wh, *p_wl;
    cudaGetSymbolAddress(&p_cnt, g_cnt);
    cudaGetSymbolAddress(&p_emb, g_emb);
    cudaGetSymbolAddress(&p_h,   g_h);
    cudaGetSymbolAddress(&p_h2,  g_h2);
    cudaGetSymbolAddress(&p_mh,  g_mh);
    cudaGetSymbolAddress(&p_ml,  g_ml);
    cudaGetSymbolAddress(&p_wh,  g_wh);
    cudaGetSymbolAddress(&p_wl,  g_wl);

    const int TPB = 256;
    const int node_warp_blocks = NN / 8;
    const int gemm_blocks      = NN / 128;

    cudaFuncSetAttribute(k_gemm_tc, cudaFuncAttributeMaxDynamicSharedMemorySize, SM_TOT);
    cudaFuncSetAttribute(k_gemm_l,  cudaFuncAttributeMaxDynamicSharedMemorySize, GL_TOT);

    // --- CSR build + weight split ---
    cudaMemsetAsync(p_cnt, 0, (size_t)NN * sizeof(int), 0);
    k_count<<<EE / TPB, TPB>>>(dst);
    k_wsplit<<<(2 * 4 * HH * HH) / TPB, TPB>>>(W_r);
    k_scan1<<<128, 256>>>();
    k_scan2<<<1, 128>>>();
    k_scan3<<<128, 256>>>();
    k_fill<<<EE / TPB, TPB>>>(src, dst, etype, norm);

    // --- init_forward ---
    k_init<<<node_warp_blocks, TPB>>>((const float4*)emb_table, gid, spo);

    // --- input projection (xinit folded into epilogue) ---
    k_gemm_tc<<<gemm_blocks, TPB, SM_TOT>>>((const float*)p_emb, W_t,
                                            spo, access_, pre, b_t, (float*)p_h);

    // --- layer 0 ---
    k_gather4<<<node_warp_blocks, TPB>>>((const float*)p_h);
    k_gemm_l<<<gemm_blocks, TPB, GL_TOT>>>((const uint16_t*)p_mh, (const uint16_t*)p_ml,
                                           (const uint16_t*)p_wh, (const uint16_t*)p_wl,
                                           b_r, (const float*)p_h, (float*)p_h2);

    // --- layer 1 ---
    k_gather4<<<node_warp_blocks, TPB>>>((const float*)p_h2);
    k_gemm_l<<<gemm_blocks, TPB, GL_TOT>>>((const uint16_t*)p_mh, (const uint16_t*)p_ml,
                                           (const uint16_t*)p_wh + 4 * HH * HH,
                                           (const uint16_t*)p_wl + 4 * HH * HH,
                                           b_r + HH, nullptr, (float*)p_h);

    // --- head ---
    k_transpose<<<(HH * HH) / TPB, TPB>>>(Wb);
    k_pool<<<BBG, HH>>>((const float*)p_h, pred);
    k_tp<<<BBG, HH>>>();
    k_score<<<BBG, HH>>>((const float*)p_h, pred, bb, out);
}

// round 10
// speedup vs baseline: 1.2277x; 1.0548x over previous
#include <cuda_runtime.h>
#include <cuda_bf16.h>
#include <cstdint>

#define NN   131072
#define EE   1048576
#define HH   128
#define VV   30000
#define VPAD 30080     // 235 * 128
#define BBG  512
#define PPG  32
#define NH   (NN*HH)

// ---------------- static device scratch ----------------
__device__ float g_ptab[VPAD * HH];    // projected embedding table
__device__ float g_h[NH];
__device__ float g_h2[NH];
__device__ uint16_t g_mh[4ULL * NH];   // mailbox hi (bf16)
__device__ uint16_t g_ml[4ULL * NH];   // mailbox lo (bf16)
__device__ uint16_t g_wh[2 * 4 * HH * HH];  // W_r hi
__device__ uint16_t g_wl[2 * 4 * HH * HH];  // W_r lo
__device__ float g_pool[BBG * HH];
__device__ float g_tp[BBG * HH];
__device__ float g_wbt[HH * HH];
// dst-keyed CSR
__device__ int  g_cnt[NN];
__device__ int  g_off[NN + 1];
__device__ int  g_cur[NN];
__device__ int  g_bsum[128];
__device__ int2 g_rec[EE];             // {src | etype<<20, norm bits}

// ---------------- helpers ----------------
__device__ __forceinline__ uint32_t smem_u32(const void* p) {
    uint32_t a;
    asm("{ .reg .u64 t; cvta.to.shared.u64 t, %1; cvt.u32.u64 %0, t; }" : "=r"(a) : "l"(p));
    return a;
}
__device__ __forceinline__ void ldsm_x4(uint32_t r[4], uint32_t addr) {
    asm volatile("ldmatrix.sync.aligned.m8n8.x4.shared.b16 {%0,%1,%2,%3}, [%4];"
                 : "=r"(r[0]), "=r"(r[1]), "=r"(r[2]), "=r"(r[3]) : "r"(addr));
}
__device__ __forceinline__ void ldsm_x4_t(uint32_t r[4], uint32_t addr) {
    asm volatile("ldmatrix.sync.aligned.m8n8.x4.trans.shared.b16 {%0,%1,%2,%3}, [%4];"
                 : "=r"(r[0]), "=r"(r[1]), "=r"(r[2]), "=r"(r[3]) : "r"(addr));
}
__device__ __forceinline__ void mma_bf16(float* c, const uint32_t a[4], const uint32_t* b) {
    asm volatile(
        "mma.sync.aligned.m16n8k16.row.col.f32.bf16.bf16.f32 "
        "{%0,%1,%2,%3}, {%4,%5,%6,%7}, {%8,%9}, {%0,%1,%2,%3};"
        : "+f"(c[0]), "+f"(c[1]), "+f"(c[2]), "+f"(c[3])
        : "r"(a[0]), "r"(a[1]), "r"(a[2]), "r"(a[3]), "r"(b[0]), "r"(b[1]));
}
__device__ __forceinline__ void split2(float a, float b, uint32_t& hi, uint32_t& lo) {
    __nv_bfloat16 ha = __float2bfloat16_rn(a);
    __nv_bfloat16 hb = __float2bfloat16_rn(b);
    __nv_bfloat16 la = __float2bfloat16_rn(a - __bfloat162float(ha));
    __nv_bfloat16 lb = __float2bfloat16_rn(b - __bfloat162float(hb));
    hi = (uint32_t)__bfloat16_as_ushort(ha) | ((uint32_t)__bfloat16_as_ushort(hb) << 16);
    lo = (uint32_t)__bfloat16_as_ushort(la) | ((uint32_t)__bfloat16_as_ushort(lb) << 16);
}
__device__ __forceinline__ void cp16(uint32_t smem, const void* g) {
    asm volatile("cp.async.cg.shared.global [%0], [%1], 16;" :: "r"(smem), "l"(g));
}

// ---------------- CSR build (dst-keyed) ----------------
__global__ void k_count(const int* __restrict__ dst) {
    int e = blockIdx.x * blockDim.x + threadIdx.x;
    if (e >= EE) return;
    atomicAdd(&g_cnt[dst[e]], 1);
}

__global__ void k_scan1() {
    __shared__ int s[256];
    int t = threadIdx.x;
    int4 v = *(const int4*)(g_cnt + blockIdx.x * 1024 + t * 4);
    s[t] = v.x + v.y + v.z + v.w;
    __syncthreads();
    for (int o = 128; o > 0; o >>= 1) {
        if (t < o) s[t] += s[t + o];
        __syncthreads();
    }
    if (t == 0) g_bsum[blockIdx.x] = s[0];
}

__global__ void k_scan2() {
    __shared__ int s[128];
    int t = threadIdx.x;
    int mine = g_bsum[t];
    s[t] = mine;
    __syncthreads();
    for (int o = 1; o < 128; o <<= 1) {
        int add = (t >= o) ? s[t - o] : 0;
        __syncthreads();
        s[t] += add;
        __syncthreads();
    }
    g_bsum[t] = s[t] - mine;
}

__global__ void k_scan3() {
    __shared__ int s[256];
    int t = threadIdx.x;
    int base = blockIdx.x * 1024 + t * 4;
    int4 v = *(const int4*)(g_cnt + base);
    int tsum = v.x + v.y + v.z + v.w;
    s[t] = tsum;
    __syncthreads();
    for (int o = 1; o < 256; o <<= 1) {
        int add = (t >= o) ? s[t - o] : 0;
        __syncthreads();
        s[t] += add;
        __syncthreads();
    }
    int o0 = s[t] - tsum + g_bsum[blockIdx.x];
    int o1 = o0 + v.x, o2 = o1 + v.y, o3 = o2 + v.z;
    *(int4*)(g_off + base) = make_int4(o0, o1, o2, o3);
    *(int4*)(g_cur + base) = make_int4(o0, o1, o2, o3);
    if (base + 4 == NN) g_off[NN] = o3 + v.w;
}

__global__ void k_fill(const int* __restrict__ src, const int* __restrict__ dst,
                       const int* __restrict__ et,  const float* __restrict__ norm) {
    int e = blockIdx.x * blockDim.x + threadIdx.x;
    if (e >= EE) return;
    int p = atomicAdd(&g_cur[dst[e]], 1);
    g_rec[p] = make_int2(src[e] | (et[e] << 20), __float_as_int(norm[e]));
}

// ---------------- weight split ----------------
__global__ void k_wsplit(const float* __restrict__ Wr) {
    int i = blockIdx.x * blockDim.x + threadIdx.x;   // 131072
    float v = Wr[i];
    __nv_bfloat16 h = __float2bfloat16_rn(v);
    g_wh[i] = __bfloat16_as_ushort(h);
    g_wl[i] = __bfloat16_as_ushort(__float2bfloat16_rn(v - __bfloat162float(h)));
}

// ---------------- projected table: ptab = emb_table @ Wt[:128] ----------------
#define SM_AHI 0
#define SM_ALO 18432
#define SM_BHI 36864
#define SM_BLO 54272
#define SM_TOT 71680

__global__ void __launch_bounds__(256, 2) k_proj(
    const float* __restrict__ A, const float* __restrict__ Wt)
{
    extern __shared__ char smem[];
    uint32_t s0 = smem_u32(smem);
    int tid = threadIdx.x, wid = tid >> 5, lane = tid & 31;
    int row0 = blockIdx.x * 128;
    int warp_m = wid & 1, warp_n = wid >> 1;

    float c[4][4][4];
#pragma unroll
    for (int i = 0; i < 4; i++)
#pragma unroll
        for (int j = 0; j < 4; j++)
#pragma unroll
            for (int q = 0; q < 4; q++) c[i][j][q] = 0.0f;

    for (int ch = 0; ch < 2; ch++) {
        if (tid < 128) {
#pragma unroll
            for (int p = 0; p < 16; p++) {
                int e = p * 128 + tid;
                int r = e >> 4, c4 = e & 15;
                int rg = min(row0 + r, VV - 1);
                float4 v = *(const float4*)(A + (size_t)rg * HH + ch * 64 + c4 * 4);
                uint32_t h0, l0, h1, l1;
                split2(v.x, v.y, h0, l0);
                split2(v.z, v.w, h1, l1);
                uint32_t off = (uint32_t)r * 144 + c4 * 8;
                *(uint2*)(smem + SM_AHI + off) = make_uint2(h0, h1);
                *(uint2*)(smem + SM_ALO + off) = make_uint2(l0, l1);
            }
        } else {
            int t = tid - 128;
            const float* gb = Wt + (size_t)(ch * 64) * HH;
#pragma unroll
            for (int p = 0; p < 16; p++) {
                int e = p * 128 + t;
                int k = e >> 5, c4 = e & 31;
                float4 v = *(const float4*)(gb + (size_t)k * HH + c4 * 4);
                uint32_t h0, l0, h1, l1;
                split2(v.x, v.y, h0, l0);
                split2(v.z, v.w, h1, l1);
                uint32_t off = (uint32_t)k * 272 + c4 * 8;
                *(uint2*)(smem + SM_BHI + off) = make_uint2(h0, h1);
                *(uint2*)(smem + SM_BLO + off) = make_uint2(l0, l1);
            }
        }
        __syncthreads();

#pragma unroll
        for (int ks = 0; ks < 4; ks++) {
            uint32_t ah[4][4], al[4][4];
#pragma unroll
            for (int mt = 0; mt < 4; mt++) {
                uint32_t row  = warp_m * 64 + mt * 16 + (lane & 15);
                uint32_t addr = s0 + SM_AHI + row * 144 + ks * 32 + ((lane >> 4) << 4);
                ldsm_x4(ah[mt], addr);
                ldsm_x4(al[mt], addr + (SM_ALO - SM_AHI));
            }
#pragma unroll
            for (int np = 0; np < 2; np++) {
                uint32_t kk   = ks * 16 + (lane & 15);
                uint32_t col  = warp_n * 32 + np * 16 + ((lane >> 4) & 1) * 8;
                uint32_t addr = s0 + SM_BHI + kk * 272 + col * 2;
                uint32_t bh[4], bl[4];
                ldsm_x4_t(bh, addr);
                ldsm_x4_t(bl, addr + (SM_BLO - SM_BHI));
#pragma unroll
                for (int mt = 0; mt < 4; mt++) {
                    mma_bf16(c[mt][np * 2],     ah[mt], bh);
                    mma_bf16(c[mt][np * 2],     al[mt], bh);
                    mma_bf16(c[mt][np * 2],     ah[mt], bl);
                    mma_bf16(c[mt][np * 2 + 1], ah[mt], bh + 2);
                    mma_bf16(c[mt][np * 2 + 1], al[mt], bh + 2);
                    mma_bf16(c[mt][np * 2 + 1], ah[mt], bl + 2);
                }
            }
        }
        __syncthreads();
    }

#pragma unroll
    for (int mt = 0; mt < 4; mt++) {
#pragma unroll
        for (int nt = 0; nt < 4; nt++) {
            int col = warp_n * 32 + nt * 8 + (lane & 3) * 2;
#pragma unroll
            for (int half = 0; half < 2; half++) {
                long row = row0 + warp_m * 64 + mt * 16 + (lane >> 2) + half * 8;
                if (row < VV)
                    *(float2*)(g_ptab + row * HH + col) =
                        make_float2(c[mt][nt][half * 2 + 0], c[mt][nt][half * 2 + 1]);
            }
        }
    }
}

// ---------------- init: h0 directly from ptab (warp per node, CSR) ----------------
__global__ void k_init2(const int* __restrict__ gid, const int* __restrict__ spo,
                        const int* __restrict__ acc_, const int* __restrict__ pre,
                        const float* __restrict__ Wt, const float* __restrict__ bt,
                        float* __restrict__ hout)
{
    __shared__ float sw[768];   // Wt tail rows (5 x 128) + bt
    for (int i = threadIdx.x; i < 768; i += blockDim.x)
        sw[i] = (i < 640) ? Wt[(size_t)(128 + (i >> 7)) * HH + (i & 127)] : bt[i - 640];
    __syncthreads();

    int node = (blockIdx.x * blockDim.x + threadIdx.x) >> 5;
    int lane = threadIdx.x & 31;
    if (node >= NN) return;
    int s0 = spo[node * 3 + 0];
    int s1 = spo[node * 3 + 1];
    int s2 = spo[node * 3 + 2];
    int beg = g_off[node], end = g_off[node + 1];

    float4 a = make_float4(0.f, 0.f, 0.f, 0.f);
    bool has_ne = false;
    for (int base = beg; base < end; base += 32) {
        int n = min(32, end - base);
        int2 r = (base + lane < end) ? g_rec[base + lane] : make_int2(-1, 0);
        for (int i = 0; i < n; i++) {
            int rx = __shfl_sync(0xffffffffu, r.x, i);
            int rn = __shfl_sync(0xffffffffu, r.y, i);
            if ((rx >> 20) != 0) continue;
            has_ne = true;
            int s = rx & 0xFFFFF;
            float nw = __int_as_float(rn);
            float4 hv = ((const float4*)g_ptab)[(size_t)gid[s] * 32 + lane];
            a.x += hv.x * nw; a.y += hv.y * nw;
            a.z += hv.z * nw; a.w += hv.w * nw;
        }
    }
    float4 e4;
    if ((s0 + s2) > 0 && has_ne) e4 = a;
    else                         e4 = ((const float4*)g_ptab)[(size_t)gid[node] * 32 + lane];

    float cf0 = (float)s0, cf1 = (float)s1, cf2 = (float)s2;
    float cf3 = (float)acc_[node], cf4 = (float)pre[node];
    int col = lane * 4;
#pragma unroll
    for (int q = 0; q < 4; q++) {
        float add = sw[640 + col + q]
                  + cf0 * sw[col + q]       + cf1 * sw[128 + col + q]
                  + cf2 * sw[256 + col + q] + cf3 * sw[384 + col + q]
                  + cf4 * sw[512 + col + q];
        (&e4.x)[q] += add;
    }
    ((float4*)hout)[(size_t)node * 32 + lane] = e4;
}

// ---------------- gather-first: 4 per-type aggregates, bf16 hi/lo out ------
__global__ void k_gather4(const float* __restrict__ h)
{
    int node = (blockIdx.x * blockDim.x + threadIdx.x) >> 5;
    int lane = threadIdx.x & 31;
    if (node >= NN) return;
    int beg = g_off[node], end = g_off[node + 1];

    float4 a0 = make_float4(0.f, 0.f, 0.f, 0.f);
    float4 a1 = a0, a2 = a0, a3 = a0;
    for (int base = beg; base < end; base += 32) {
        int n = min(32, end - base);
        int2 r = (base + lane < end) ? g_rec[base + lane] : make_int2(0, 0);
        for (int i = 0; i < n; i++) {
            int rx = __shfl_sync(0xffffffffu, r.x, i);
            int rn = __shfl_sync(0xffffffffu, r.y, i);
            int s = rx & 0xFFFFF;
            int t = rx >> 20;
            float nw = __int_as_float(rn);
            float4 v = *(const float4*)(h + (size_t)s * HH + lane * 4);
            switch (t) {
            case 0: a0.x += v.x*nw; a0.y += v.y*nw; a0.z += v.z*nw; a0.w += v.w*nw; break;
            case 1: a1.x += v.x*nw; a1.y += v.y*nw; a1.z += v.z*nw; a1.w += v.w*nw; break;
            case 2: a2.x += v.x*nw; a2.y += v.y*nw; a2.z += v.z*nw; a2.w += v.w*nw; break;
            default:a3.x += v.x*nw; a3.y += v.y*nw; a3.z += v.z*nw; a3.w += v.w*nw; break;
            }
        }
    }
    size_t o = (size_t)node * 32 + lane;
    float4 acc[4] = {a0, a1, a2, a3};
#pragma unroll
    for (int t = 0; t < 4; t++) {
        uint32_t h0, l0, h1, l1;
        split2(acc[t].x, acc[t].y, h0, l0);
        split2(acc[t].z, acc[t].w, h1, l1);
        ((uint2*)(g_mh + (size_t)t * NH))[o] = make_uint2(h0, h1);
        ((uint2*)(g_ml + (size_t)t * NH))[o] = make_uint2(l0, l1);
    }
}

// ---------------- layer GEMM: cp.async double-buffered, K=512 over 16 chunks ----
#define GL_AHI 0
#define GL_ALO 10240
#define GL_BHI 20480
#define GL_BLO 29184
#define GL_BUF 37888
#define GL_TOT 75776

__global__ void __launch_bounds__(256, 2) k_gemm_l(
    const uint16_t* __restrict__ mh, const uint16_t* __restrict__ ml,
    const uint16_t* __restrict__ wh, const uint16_t* __restrict__ wl,
    const float* __restrict__ bias, const float* __restrict__ resid,
    float* __restrict__ C)
{
    extern __shared__ char smem[];
    uint32_t s0 = smem_u32(smem);
    int tid = threadIdx.x, wid = tid >> 5, lane = tid & 31;
    int row0 = blockIdx.x * 128;
    int warp_m = wid & 1, warp_n = wid >> 1;

    float c[4][4][4];
#pragma unroll
    for (int i = 0; i < 4; i++)
#pragma unroll
        for (int j = 0; j < 4; j++)
#pragma unroll
            for (int q = 0; q < 4; q++) c[i][j][q] = 0.0f;

    auto load_chunk = [&](int ch, int buf) {
        int t = ch >> 2, sub = ch & 3;
        const uint16_t* mhb = mh + (size_t)t * NH + (size_t)row0 * HH + sub * 32;
        const uint16_t* mlb = ml + (size_t)t * NH + (size_t)row0 * HH + sub * 32;
        const uint16_t* whb = wh + (size_t)t * HH * HH + (size_t)(sub * 32) * HH;
        const uint16_t* wlb = wl + (size_t)t * HH * HH + (size_t)(sub * 32) * HH;
        uint32_t sb = s0 + buf * GL_BUF;
#pragma unroll
        for (int q = 0; q < 2; q++) {
            int s = q * 256 + tid;
            int r = s >> 2, part = s & 3;
            cp16(sb + GL_AHI + r * 80 + part * 16, mhb + (size_t)r * HH + part * 8);
            cp16(sb + GL_ALO + r * 80 + part * 16, mlb + (size_t)r * HH + part * 8);
        }
#pragma unroll
        for (int q = 0; q < 2; q++) {
            int s = q * 256 + tid;
            int r = s >> 4, part = s & 15;
            cp16(sb + GL_BHI + r * 272 + part * 16, whb + (size_t)r * HH + part * 8);
            cp16(sb + GL_BLO + r * 272 + part * 16, wlb + (size_t)r * HH + part * 8);
        }
    };

    load_chunk(0, 0);
    asm volatile("cp.async.commit_group;" ::: "memory");

    for (int ch = 0; ch < 16; ch++) {
        if (ch + 1 < 16) {
            load_chunk(ch + 1, (ch + 1) & 1);
            asm volatile("cp.async.commit_group;" ::: "memory");
            asm volatile("cp.async.wait_group 1;" ::: "memory");
        } else {
            asm volatile("cp.async.wait_group 0;" ::: "memory");
        }
        __syncthreads();

        uint32_t sb = s0 + (ch & 1) * GL_BUF;
#pragma unroll
        for (int ks = 0; ks < 2; ks++) {
            uint32_t ah[4][4], al[4][4];
#pragma unroll
            for (int mt = 0; mt < 4; mt++) {
                uint32_t row  = warp_m * 64 + mt * 16 + (lane & 15);
                uint32_t addr = sb + GL_AHI + row * 80 + ks * 32 + ((lane >> 4) << 4);
                ldsm_x4(ah[mt], addr);
                ldsm_x4(al[mt], addr + (GL_ALO - GL_AHI));
            }
#pragma unroll
            for (int np = 0; np < 2; np++) {
                uint32_t kk   = ks * 16 + (lane & 15);
                uint32_t col  = warp_n * 32 + np * 16 + ((lane >> 4) & 1) * 8;
                uint32_t addr = sb + GL_BHI + kk * 272 + col * 2;
                uint32_t bh[4], bl[4];
                ldsm_x4_t(bh, addr);
                ldsm_x4_t(bl, addr + (GL_BLO - GL_BHI));
#pragma unroll
                for (int mt = 0; mt < 4; mt++) {
                    mma_bf16(c[mt][np * 2],     ah[mt], bh);
                    mma_bf16(c[mt][np * 2],     al[mt], bh);
                    mma_bf16(c[mt][np * 2],     ah[mt], bl);
                    mma_bf16(c[mt][np * 2 + 1], ah[mt], bh + 2);
                    mma_bf16(c[mt][np * 2 + 1], al[mt], bh + 2);
                    mma_bf16(c[mt][np * 2 + 1], ah[mt], bl + 2);
                }
            }
        }
        __syncthreads();
    }

#pragma unroll
    for (int mt = 0; mt < 4; mt++) {
#pragma unroll
        for (int nt = 0; nt < 4; nt++) {
            int col = warp_n * 32 + nt * 8 + (lane & 3) * 2;
            float2 bv = *(const float2*)(bias + col);
#pragma unroll
            for (int half = 0; half < 2; half++) {
                long row  = row0 + warp_m * 64 + mt * 16 + (lane >> 2) + half * 8;
                long base = row * HH + col;
                float2 v;
                v.x = fmaxf(c[mt][nt][half * 2 + 0] + bv.x, 0.f);
                v.y = fmaxf(c[mt][nt][half * 2 + 1] + bv.y, 0.f);
                if (resid) {
                    float2 rr = *(const float2*)(resid + base);
                    v.x += rr.x; v.y += rr.y;
                }
                *(float2*)(C + base) = v;
            }
        }
    }
}

// ---------------- head kernels ----------------
__global__ void k_transpose(const float* __restrict__ Wb) {
    int idx = blockIdx.x * blockDim.x + threadIdx.x;
    if (idx >= HH * HH) return;
    int r = idx >> 7, c = idx & 127;
    g_wbt[c * HH + r] = Wb[idx];
}

__global__ void k_pool(const float* __restrict__ h, const int* __restrict__ pred) {
    int b = blockIdx.x, j = threadIdx.x;
    float acc = 0.0f;
#pragma unroll 4
    for (int p = 0; p < PPG; p++) {
        int node = pred[b * PPG + p];
        acc += h[(size_t)node * HH + j];
    }
    g_pool[b * HH + j] = acc * (1.0f / PPG);
}

__global__ void k_tp() {
    int b = blockIdx.x, hrow = threadIdx.x;
    __shared__ float ps[HH];
    ps[hrow] = g_pool[b * HH + hrow];
    __syncthreads();
    float acc = 0.0f;
#pragma unroll 8
    for (int k = 0; k < HH; k++)
        acc += g_wbt[(size_t)k * HH + hrow] * ps[k];
    g_tp[b * HH + hrow] = acc;
}

__global__ void k_score(const float* __restrict__ h, const int* __restrict__ pred,
                        const float* __restrict__ bbp, float* __restrict__ out)
{
    int b = blockIdx.x;
    int tid = threadIdx.x;
    __shared__ __align__(16) float tps[HH];
    __shared__ float sc[PPG];
    tps[tid] = g_tp[b * HH + tid];
    __syncthreads();
    int warp = tid >> 5, lane = tid & 31;
    float4 tv = ((const float4*)tps)[lane];
    for (int p = warp; p < PPG; p += 4) {
        int node = pred[b * PPG + p];
        float4 hv = ((const float4*)h)[(size_t)node * 32 + lane];
        float d = hv.x * tv.x + hv.y * tv.y + hv.z * tv.z + hv.w * tv.w;
#pragma unroll
        for (int o = 16; o > 0; o >>= 1) d += __shfl_xor_sync(0xffffffffu, d, o);
        if (lane == 0) sc[p] = d + bbp[0];
    }
    __syncthreads();
    if (tid < 32) {
        float v = sc[tid];
        float m = v;
#pragma unroll
        for (int o = 16; o > 0; o >>= 1) m = fmaxf(m, __shfl_xor_sync(0xffffffffu, m, o));
        float e = expf(v - m);
        float s = e;
#pragma unroll
        for (int o = 16; o > 0; o >>= 1) s += __shfl_xor_sync(0xffffffffu, s, o);
        out[b * PPG + tid] = v - m - logf(s);
    }
}

// ---------------- launch ----------------
extern "C" void kernel_launch(void* const* d_in, const int* in_sizes, int n_in,
                              void* d_out, int out_size)
{
    (void)in_sizes; (void)n_in; (void)out_size;
    const float* emb_table = (const float*)d_in[0];
    const float* W_t       = (const float*)d_in[1];
    const float* b_t       = (const float*)d_in[2];
    const float* W_r       = (const float*)d_in[3];
    const float* b_r       = (const float*)d_in[4];
    const float* Wb        = (const float*)d_in[5];
    const float* bb        = (const float*)d_in[6];
    const float* norm      = (const float*)d_in[7];
    const int*   gid       = (const int*)d_in[8];
    const int*   spo       = (const int*)d_in[9];
    const int*   access_   = (const int*)d_in[10];
    const int*   pre       = (const int*)d_in[11];
    const int*   src       = (const int*)d_in[12];
    const int*   dst       = (const int*)d_in[13];
    const int*   etype     = (const int*)d_in[14];
    const int*   pred      = (const int*)d_in[15];
    float* out = (float*)d_out;

    void *p_cnt, *p_h, *p_h2, *p_mh, *p_ml, *p_wh, *p_wl;
    cudaGetSymbolAddress(&p_cnt, g_cnt);
    cudaGetSymbolAddress(&p_h,   g_h);
    cudaGetSymbolAddress(&p_h2,  g_h2);
    cudaGetSymbolAddress(&p_mh,  g_mh);
    cudaGetSymbolAddress(&p_ml,  g_ml);
    cudaGetSymbolAddress(&p_wh,  g_wh);
    cudaGetSymbolAddress(&p_wl,  g_wl);

    const int TPB = 256;
    const int node_warp_blocks = NN / 8;
    const int gemm_blocks      = NN / 128;
    const int proj_blocks      = VPAD / 128;   // 235

    cudaFuncSetAttribute(k_proj,   cudaFuncAttributeMaxDynamicSharedMemorySize, SM_TOT);
    cudaFuncSetAttribute(k_gemm_l, cudaFuncAttributeMaxDynamicSharedMemorySize, GL_TOT);

    // --- CSR build + weight split + table projection (independent of CSR) ---
    cudaMemsetAsync(p_cnt, 0, (size_t)NN * sizeof(int), 0);
    k_count<<<EE / TPB, TPB>>>(dst);
    k_wsplit<<<(2 * 4 * HH * HH) / TPB, TPB>>>(W_r);
    k_proj<<<proj_blocks, TPB, SM_TOT>>>(emb_table, W_t);
    k_scan1<<<128, 256>>>();
    k_scan2<<<1, 128>>>();
    k_scan3<<<128, 256>>>();
    k_fill<<<EE / TPB, TPB>>>(src, dst, etype, norm);

    // --- init: h0 directly (projection + ne-aggregate + xinit fused) ---
    k_init2<<<node_warp_blocks, TPB>>>(gid, spo, access_, pre, W_t, b_t, (float*)p_h);

    // --- layer 0 ---
    k_gather4<<<node_warp_blocks, TPB>>>((const float*)p_h);
    k_gemm_l<<<gemm_blocks, TPB, GL_TOT>>>((const uint16_t*)p_mh, (const uint16_t*)p_ml,
                                           (const uint16_t*)p_wh, (const uint16_t*)p_wl,
                                           b_r, (const float*)p_h, (float*)p_h2);

    // --- layer 1 ---
    k_gather4<<<node_warp_blocks, TPB>>>((const float*)p_h2);
    k_gemm_l<<<gemm_blocks, TPB, GL_TOT>>>((const uint16_t*)p_mh, (const uint16_t*)p_ml,
                                           (const uint16_t*)p_wh + 4 * HH * HH,
                                           (const uint16_t*)p_wl + 4 * HH * HH,
                                           b_r + HH, nullptr, (float*)p_h);

    // --- head ---
    k_transpose<<<(HH * HH) / TPB, TPB>>>(Wb);
    k_pool<<<BBG, HH>>>((const float*)p_h, pred);
    k_tp<<<BBG, HH>>>();
    k_score<<<BBG, HH>>>((const float*)p_h, pred, bb, out);
}